// round 7
// baseline (speedup 1.0000x reference)
#include <cuda_runtime.h>
#include <math.h>

// Problem constants
#define B_ 4
#define T_ 2048
#define C_ 2048
#define H_ 16
#define DH 128
#define THREE_C (3 * C_)

// Scratch (device globals — allocation-free)
__device__ float g_qkv[(size_t)B_ * T_ * THREE_C];  // 192 MiB
__device__ float g_y[(size_t)B_ * T_ * C_];         // 64 MiB

// ---------------------------------------------------------------------------
// SGEMM: C = A(MxK) * B(KxN) + bias(N), row-major, fp32.
// 128x128 block tile, BK=8, 256 threads, 8x8 per thread (4x4 quads).
// Requires M%128==0, N%128==0, K%8==0.
// ---------------------------------------------------------------------------
__global__ __launch_bounds__(256, 2)
void sgemm_bias_kernel(const float* __restrict__ A, const float* __restrict__ Bm,
                       const float* __restrict__ bias, float* __restrict__ Cm,
                       int M, int N, int K)
{
    const int BK = 8;
    __shared__ float As[BK][128];
    __shared__ float Bs[BK][128];

    const int tid = threadIdx.x;
    const int tr = tid >> 4;        // 0..15
    const int tc = tid & 15;        // 0..15
    const int rowBase = blockIdx.y * 128;
    const int colBase = blockIdx.x * 128;

    const int aRow = tid >> 1;            // 0..127
    const int aCol = (tid & 1) * 4;       // 0 or 4
    const int bRow = tid >> 5;            // 0..7
    const int bCol = (tid & 31) * 4;      // 0..124

    const float* Aptr = A + (size_t)(rowBase + aRow) * K + aCol;
    const float* Bptr = Bm + (size_t)bRow * N + colBase + bCol;

    float acc[8][8];
#pragma unroll
    for (int i = 0; i < 8; i++)
#pragma unroll
        for (int j = 0; j < 8; j++) acc[i][j] = 0.f;

    for (int k0 = 0; k0 < K; k0 += BK) {
        float4 a4 = *(const float4*)(Aptr + k0);
        As[aCol + 0][aRow] = a4.x;
        As[aCol + 1][aRow] = a4.y;
        As[aCol + 2][aRow] = a4.z;
        As[aCol + 3][aRow] = a4.w;
        *(float4*)&Bs[bRow][bCol] = *(const float4*)(Bptr + (size_t)k0 * N);
        __syncthreads();

#pragma unroll
        for (int k = 0; k < BK; k++) {
            float ra[8], rb[8];
            *(float4*)&ra[0] = *(const float4*)&As[k][tr * 4];
            *(float4*)&ra[4] = *(const float4*)&As[k][64 + tr * 4];
            *(float4*)&rb[0] = *(const float4*)&Bs[k][tc * 4];
            *(float4*)&rb[4] = *(const float4*)&Bs[k][64 + tc * 4];
#pragma unroll
            for (int i = 0; i < 8; i++)
#pragma unroll
                for (int j = 0; j < 8; j++)
                    acc[i][j] = fmaf(ra[i], rb[j], acc[i][j]);
        }
        __syncthreads();
    }

    // Epilogue: + bias, write two float4 per owned row
    float4 bb0 = *(const float4*)&bias[colBase + tc * 4];
    float4 bb1 = *(const float4*)&bias[colBase + 64 + tc * 4];
#pragma unroll
    for (int i = 0; i < 8; i++) {
        int r = rowBase + ((i < 4) ? (tr * 4 + i) : (64 + tr * 4 + i - 4));
        float4 o0, o1;
        o0.x = acc[i][0] + bb0.x; o0.y = acc[i][1] + bb0.y;
        o0.z = acc[i][2] + bb0.z; o0.w = acc[i][3] + bb0.w;
        o1.x = acc[i][4] + bb1.x; o1.y = acc[i][5] + bb1.y;
        o1.z = acc[i][6] + bb1.z; o1.w = acc[i][7] + bb1.w;
        *(float4*)(Cm + (size_t)r * N + colBase + tc * 4) = o0;
        *(float4*)(Cm + (size_t)r * N + colBase + 64 + tc * 4) = o1;
    }
}

// ---------------------------------------------------------------------------
// RoPE in-place on q and k slices of g_qkv. Rotation over the FULL C dim:
// pair p uses channels (2p, 2p+1), inv_freq = theta^(-2p/C), angle = t*inv.
// Cody-Waite reduction keeps sincos accurate for angles up to ~2047 rad.
// ---------------------------------------------------------------------------
__global__ void rope_kernel(float* __restrict__ qkv)
{
    const size_t NP = (size_t)B_ * T_ * (C_ / 2);
    size_t idx = (size_t)blockIdx.x * blockDim.x + threadIdx.x;
    if (idx >= 2 * NP) return;
    int sel = (idx >= NP) ? 1 : 0;   // 0 = q, 1 = k
    size_t r = sel ? (idx - NP) : idx;
    int p = (int)(r % (C_ / 2));
    size_t bt = r / (C_ / 2);
    int t = (int)(bt % T_);

    float e = (float)(2 * p) * (1.0f / (float)C_);
    float inv = expf(-9.210340371976184f * e);   // theta^(-2p/C), ln(1e4)
    float ang = (float)t * inv;

    // reduce ang mod 2*pi (Cody-Waite, 2 terms)
    float kq = rintf(ang * 0.15915494309189535f);
    float rr = fmaf(-kq, 6.28318548202514648f, ang);
    rr = fmaf(-kq, -1.7484556000744083e-7f, rr);
    float s, c;
    sincosf(rr, &s, &c);

    float* ptr = qkv + bt * (size_t)THREE_C + (size_t)sel * C_ + 2 * p;
    float2 v = *(float2*)ptr;
    float2 o;
    o.x = v.x * c - v.y * s;
    o.y = v.x * s + v.y * c;
    *(float2*)ptr = o;
}

// ---------------------------------------------------------------------------
// Flash attention, fp32, causal. BQ=64 q rows, BKV=64 kv rows, dh=128.
// 256 threads. Thread (sq=tid/16, sk=tid%16):
//   phase 1 owns S rows sq*4+{0..3}, cols sk+16*{0..3}
//   phase 2 owns O rows sq*4+{0..3}, d cols sk*4+{0..3} and 64+sk*4+{0..3}
// Row softmax stats reduced across the 16-lane sk group via shfl_xor.
// ---------------------------------------------------------------------------
#define BQ 64
#define BKV 64
#define PAD 132
#define ATTN_SMEM_FLOATS (3 * BQ * PAD + BQ * BKV)

__global__ __launch_bounds__(256, 1)
void attn_kernel(const float* __restrict__ qkv, float* __restrict__ y)
{
    extern __shared__ float sm[];
    float* Qs = sm;                       // 64 x PAD
    float* Ks = Qs + BQ * PAD;            // 64 x PAD
    float* Vs = Ks + BKV * PAD;           // 64 x PAD
    float* Ps = Vs + BKV * PAD;           // 64 x 64

    const int qt = blockIdx.x;
    const int h  = blockIdx.y;
    const int b  = blockIdx.z;
    const int q0 = qt * BQ;
    const int tid = threadIdx.x;
    const int sq = tid >> 4;
    const int sk = tid & 15;
    const float SCALE = 0.08838834764831845f;  // 1/sqrt(128)

    // Load Q tile (pre-scaled)
    {
        int lane = tid & 31, rofs = tid >> 5;
#pragma unroll
        for (int it = 0; it < 8; it++) {
            int row = rofs + it * 8;
            size_t g = ((size_t)(b * T_ + q0 + row)) * THREE_C + h * DH + lane * 4;
            float4 v = *(const float4*)(qkv + g);
            float* dst = &Qs[row * PAD + lane * 4];
            dst[0] = v.x * SCALE; dst[1] = v.y * SCALE;
            dst[2] = v.z * SCALE; dst[3] = v.w * SCALE;
        }
    }

    float m[4], l[4], O[4][8];
#pragma unroll
    for (int i = 0; i < 4; i++) {
        m[i] = -INFINITY; l[i] = 0.f;
#pragma unroll
        for (int j = 0; j < 8; j++) O[i][j] = 0.f;
    }

    for (int jt = 0; jt <= qt; jt++) {
        const int k0 = jt * BKV;
        __syncthreads();   // prior P*V done reading Ps/Vs
        // Load K, V tiles
        {
            int lane = tid & 31, rofs = tid >> 5;
#pragma unroll
            for (int it = 0; it < 8; it++) {
                int row = rofs + it * 8;
                size_t gk = ((size_t)(b * T_ + k0 + row)) * THREE_C + C_ + h * DH + lane * 4;
                *(float4*)&Ks[row * PAD + lane * 4] = *(const float4*)(qkv + gk);
                *(float4*)&Vs[row * PAD + lane * 4] = *(const float4*)(qkv + gk + C_);
            }
        }
        __syncthreads();

        // S = (Q*scale) @ K^T
        float Sv[4][4];
#pragma unroll
        for (int i = 0; i < 4; i++)
#pragma unroll
            for (int j = 0; j < 4; j++) Sv[i][j] = 0.f;

#pragma unroll 8
        for (int dd = 0; dd < DH; dd += 4) {
            float4 q4[4], k4[4];
#pragma unroll
            for (int i = 0; i < 4; i++)
                q4[i] = *(const float4*)&Qs[(sq * 4 + i) * PAD + dd];
#pragma unroll
            for (int j = 0; j < 4; j++)
                k4[j] = *(const float4*)&Ks[(sk + 16 * j) * PAD + dd];
#pragma unroll
            for (int i = 0; i < 4; i++)
#pragma unroll
                for (int j = 0; j < 4; j++) {
                    Sv[i][j] = fmaf(q4[i].x, k4[j].x, Sv[i][j]);
                    Sv[i][j] = fmaf(q4[i].y, k4[j].y, Sv[i][j]);
                    Sv[i][j] = fmaf(q4[i].z, k4[j].z, Sv[i][j]);
                    Sv[i][j] = fmaf(q4[i].w, k4[j].w, Sv[i][j]);
                }
        }

        // Causal mask on the diagonal tile
        if (jt == qt) {
#pragma unroll
            for (int i = 0; i < 4; i++) {
                int qg = sq * 4 + i;
#pragma unroll
                for (int j = 0; j < 4; j++)
                    if (sk + 16 * j > qg) Sv[i][j] = -INFINITY;
            }
        }

        // Online softmax update + write P to smem
#pragma unroll
        for (int i = 0; i < 4; i++) {
            float mt = fmaxf(fmaxf(Sv[i][0], Sv[i][1]), fmaxf(Sv[i][2], Sv[i][3]));
#pragma unroll
            for (int o = 8; o >= 1; o >>= 1)
                mt = fmaxf(mt, __shfl_xor_sync(0xffffffffu, mt, o));
            float mn = fmaxf(m[i], mt);
            float corr = expf(m[i] - mn);   // m=-inf -> 0
            float ps[4], rs = 0.f;
#pragma unroll
            for (int j = 0; j < 4; j++) {
                ps[j] = expf(Sv[i][j] - mn);
                rs += ps[j];
            }
#pragma unroll
            for (int o = 8; o >= 1; o >>= 1)
                rs += __shfl_xor_sync(0xffffffffu, rs, o);
            l[i] = l[i] * corr + rs;
            m[i] = mn;
#pragma unroll
            for (int j = 0; j < 8; j++) O[i][j] *= corr;
#pragma unroll
            for (int j = 0; j < 4; j++)
                Ps[(sq * 4 + i) * BKV + sk + 16 * j] = ps[j];
        }
        __syncthreads();

        // O += P @ V
#pragma unroll 2
        for (int kk = 0; kk < BKV; kk += 4) {
            float pr[4][4];
#pragma unroll
            for (int i = 0; i < 4; i++)
                *(float4*)pr[i] = *(const float4*)&Ps[(sq * 4 + i) * BKV + kk];
#pragma unroll
            for (int t4 = 0; t4 < 4; t4++) {
                float4 va = *(const float4*)&Vs[(kk + t4) * PAD + sk * 4];
                float4 vb = *(const float4*)&Vs[(kk + t4) * PAD + 64 + sk * 4];
#pragma unroll
                for (int i = 0; i < 4; i++) {
                    float p = pr[i][t4];
                    O[i][0] = fmaf(p, va.x, O[i][0]);
                    O[i][1] = fmaf(p, va.y, O[i][1]);
                    O[i][2] = fmaf(p, va.z, O[i][2]);
                    O[i][3] = fmaf(p, va.w, O[i][3]);
                    O[i][4] = fmaf(p, vb.x, O[i][4]);
                    O[i][5] = fmaf(p, vb.y, O[i][5]);
                    O[i][6] = fmaf(p, vb.z, O[i][6]);
                    O[i][7] = fmaf(p, vb.w, O[i][7]);
                }
            }
        }
    }

    // Normalize and write y (B,T,C) with c = h*DH + d
#pragma unroll
    for (int i = 0; i < 4; i++) {
        float inv_l = 1.f / l[i];
        size_t g = ((size_t)(b * T_ + q0 + sq * 4 + i)) * C_ + h * DH;
        float4 o0, o1;
        o0.x = O[i][0] * inv_l; o0.y = O[i][1] * inv_l;
        o0.z = O[i][2] * inv_l; o0.w = O[i][3] * inv_l;
        o1.x = O[i][4] * inv_l; o1.y = O[i][5] * inv_l;
        o1.z = O[i][6] * inv_l; o1.w = O[i][7] * inv_l;
        *(float4*)(y + g + sk * 4) = o0;
        *(float4*)(y + g + 64 + sk * 4) = o1;
    }
}

// ---------------------------------------------------------------------------
// Launch
// ---------------------------------------------------------------------------
extern "C" void kernel_launch(void* const* d_in, const int* in_sizes, int n_in,
                              void* d_out, int out_size)
{
    (void)in_sizes; (void)n_in; (void)out_size;
    const float* x      = (const float*)d_in[0];
    const float* w_qkv  = (const float*)d_in[1];
    const float* b_qkv  = (const float*)d_in[2];
    const float* w_proj = (const float*)d_in[3];
    const float* b_proj = (const float*)d_in[4];
    float* out = (float*)d_out;

    void* p_qkv = nullptr;
    void* p_y = nullptr;
    cudaGetSymbolAddress(&p_qkv, g_qkv);
    cudaGetSymbolAddress(&p_y, g_y);
    float* qkv = (float*)p_qkv;
    float* y   = (float*)p_y;

    const int M = B_ * T_;  // 8192

    // 1) QKV = x @ w_qkv + b_qkv
    {
        dim3 grid(3 * C_ / 128, M / 128);
        sgemm_bias_kernel<<<grid, 256>>>(x, w_qkv, b_qkv, qkv, M, 3 * C_, C_);
    }

    // 2) RoPE in-place on q and k
    {
        size_t total = 2ull * B_ * T_ * (C_ / 2);
        int threads = 256;
        int blocks = (int)((total + threads - 1) / threads);
        rope_kernel<<<blocks, threads>>>(qkv);
    }

    // 3) Causal flash attention -> y (B,T,C)
    {
        static int smem_set = 0;
        size_t smem = ATTN_SMEM_FLOATS * sizeof(float);
        cudaFuncSetAttribute(attn_kernel, cudaFuncAttributeMaxDynamicSharedMemorySize,
                             (int)smem);
        (void)smem_set;
        dim3 grid(T_ / BQ, H_, B_);
        attn_kernel<<<grid, 256, smem>>>(qkv, y);
    }

    // 4) out = y @ w_proj + b_proj
    {
        dim3 grid(C_ / 128, M / 128);
        sgemm_bias_kernel<<<grid, 256>>>(y, w_proj, b_proj, out, M, C_, C_);
    }
}

// round 9
// speedup vs baseline: 1.8316x; 1.8316x over previous
#include <cuda_runtime.h>
#include <cuda_bf16.h>
#include <math.h>
#include <stdint.h>

// Problem constants
#define B_ 4
#define T_ 2048
#define C_ 2048
#define H_ 16
#define DH 128
#define THREE_C (3 * C_)
#define M_ (B_ * T_)   // 8192

// ---------------------------------------------------------------------------
// Device-global scratch (allocation-free)
// ---------------------------------------------------------------------------
__device__ float g_qkv[(size_t)B_ * T_ * THREE_C];          // 192 MiB
__device__ float g_y[(size_t)B_ * T_ * C_];                 // 64 MiB
__device__ __nv_bfloat16 g_xc_h[(size_t)M_ * C_];
__device__ __nv_bfloat16 g_xc_l[(size_t)M_ * C_];
__device__ __nv_bfloat16 g_yc_h[(size_t)M_ * C_];
__device__ __nv_bfloat16 g_yc_l[(size_t)M_ * C_];
__device__ __nv_bfloat16 g_wq_h[(size_t)THREE_C * C_];      // w_qkv^T [6144,2048]
__device__ __nv_bfloat16 g_wq_l[(size_t)THREE_C * C_];
__device__ __nv_bfloat16 g_wp_h[(size_t)C_ * C_];           // w_proj^T [2048,2048]
__device__ __nv_bfloat16 g_wp_l[(size_t)C_ * C_];

// ---------------------------------------------------------------------------
// Helpers
// ---------------------------------------------------------------------------
__device__ __forceinline__ uint32_t smem_u32(const void* p) {
    uint32_t a;
    asm("{ .reg .u64 t; cvta.to.shared.u64 t, %1; cvt.u32.u64 %0, t; }"
        : "=r"(a) : "l"(p));
    return a;
}
static __device__ __forceinline__ uint32_t sw128(uint32_t x) {
    return x ^ ((x >> 3) & 0x70);
}
__device__ __forceinline__ void cpa16(uint32_t s, const void* g) {
    asm volatile("cp.async.cg.shared.global [%0], [%1], 16;" :: "r"(s), "l"(g));
}
#define CP_COMMIT() asm volatile("cp.async.commit_group;" ::: "memory")
#define CP_WAIT1()  asm volatile("cp.async.wait_group 1;" ::: "memory")

__device__ __forceinline__ void ldm4(uint32_t* r, uint32_t addr) {
    asm volatile("ldmatrix.sync.aligned.m8n8.x4.shared.b16 {%0,%1,%2,%3}, [%4];"
                 : "=r"(r[0]), "=r"(r[1]), "=r"(r[2]), "=r"(r[3]) : "r"(addr));
}
__device__ __forceinline__ void mma16816(float* d, const uint32_t* a,
                                         uint32_t b0, uint32_t b1) {
    asm volatile(
        "mma.sync.aligned.m16n8k16.row.col.f32.bf16.bf16.f32 "
        "{%0,%1,%2,%3}, {%4,%5,%6,%7}, {%8,%9}, {%0,%1,%2,%3};"
        : "+f"(d[0]), "+f"(d[1]), "+f"(d[2]), "+f"(d[3])
        : "r"(a[0]), "r"(a[1]), "r"(a[2]), "r"(a[3]), "r"(b0), "r"(b1));
}

// ---------------------------------------------------------------------------
// Elementwise fp32 -> bf16 (hi, lo) split. n8 = elements/8.
// ---------------------------------------------------------------------------
__global__ void convert_hilo(const float* __restrict__ X,
                             __nv_bfloat16* __restrict__ Hh,
                             __nv_bfloat16* __restrict__ Hl, long n8)
{
    long i = (long)blockIdx.x * blockDim.x + threadIdx.x;
    if (i >= n8) return;
    float4 a = ((const float4*)X)[i * 2 + 0];
    float4 b = ((const float4*)X)[i * 2 + 1];
    float v[8] = {a.x, a.y, a.z, a.w, b.x, b.y, b.z, b.w};
    union { __nv_bfloat16 e[8]; uint4 u; } ph, pl;
#pragma unroll
    for (int j = 0; j < 8; j++) {
        __nv_bfloat16 h = __float2bfloat16(v[j]);
        ph.e[j] = h;
        pl.e[j] = __float2bfloat16(v[j] - __bfloat162float(h));
    }
    ((uint4*)Hh)[i] = ph.u;
    ((uint4*)Hl)[i] = pl.u;
}

// ---------------------------------------------------------------------------
// Transpose + split: W[K,N] fp32 row-major -> Th/Tl [N,K] bf16 row-major
// ---------------------------------------------------------------------------
__global__ void wconv(const float* __restrict__ W, __nv_bfloat16* __restrict__ Th,
                      __nv_bfloat16* __restrict__ Tl, int K, int N)
{
    __shared__ float ts[32][33];
    int n0 = blockIdx.x * 32, k0 = blockIdx.y * 32;
    int tx = threadIdx.x, ty = threadIdx.y;
    for (int i = ty; i < 32; i += 8)
        ts[i][tx] = W[(size_t)(k0 + i) * N + n0 + tx];
    __syncthreads();
    for (int i = ty; i < 32; i += 8) {
        float v = ts[tx][i];   // W[k0+tx][n0+i]
        __nv_bfloat16 h = __float2bfloat16(v);
        __nv_bfloat16 l = __float2bfloat16(v - __bfloat162float(h));
        size_t o = (size_t)(n0 + i) * K + k0 + tx;
        Th[o] = h;
        Tl[o] = l;
    }
}

// ---------------------------------------------------------------------------
// HMMA bf16x3 GEMM: C[M,N] = (Ah+Al)[M,K] x ((Bh+Bl)[N,K])^T + bias
// D += Ah*Bh + Ah*Bl + Al*Bh  (fp32 accumulate; Al*Bl dropped, ~2^-16 rel)
// CTA 128x128, BK=64 bf16, 3-stage cp.async pipeline, 256 threads (8 warps).
// SMEM tiles SW128-swizzled (128B rows), fragments via ldmatrix.x4.
// ---------------------------------------------------------------------------
#define GEMM_THREADS 256
#define BKc 64
#define AT_BYTES 16384              // 128 rows x 128B
#define A_H_OFF 0
#define A_L_OFF 16384
#define B_H_OFF 32768
#define B_L_OFF 49152
#define STG_BYTES 65536
#define STAGES 3
#define GEMM_DSM (STAGES * STG_BYTES + 1024)

__global__ __launch_bounds__(GEMM_THREADS, 1)
void gemm_hmma_bf16x3(const __nv_bfloat16* __restrict__ Ah,
                      const __nv_bfloat16* __restrict__ Al,
                      const __nv_bfloat16* __restrict__ Bh,
                      const __nv_bfloat16* __restrict__ Bl,
                      const float* __restrict__ bias, float* __restrict__ Cm,
                      int N, int K)
{
    extern __shared__ char dsm[];
    const uint32_t raw = smem_u32(dsm);
    const uint32_t sb = (raw + 1023u) & ~1023u;   // 1KB-align for SW128

    const int tid = threadIdx.x;
    const int wid = tid >> 5, lane = tid & 31;
    const int wm = (wid & 3) * 32;       // warp row offset in CTA tile
    const int wn = (wid >> 2) * 64;      // warp col offset
    const int rowBase = blockIdx.y * 128;
    const int colBase = blockIdx.x * 128;
    const int nch = K / BKc;             // 32

    // ---- stage loader: 16 cp.async x 16B per thread ----
    auto load_stage = [&](int st, int k0) {
        uint32_t sbase = sb + st * STG_BYTES;
#pragma unroll
        for (int rep = 0; rep < 4; rep++) {
            int i = tid + rep * GEMM_THREADS;   // [0,1024)
            int row = i >> 3, cc = i & 7;
            uint32_t so = sw128((uint32_t)(row * 128 + cc * 16));
            size_t ga = (size_t)(rowBase + row) * K + k0 + cc * 8;
            size_t gb = (size_t)(colBase + row) * K + k0 + cc * 8;
            cpa16(sbase + A_H_OFF + so, Ah + ga);
            cpa16(sbase + A_L_OFF + so, Al + ga);
            cpa16(sbase + B_H_OFF + so, Bh + gb);
            cpa16(sbase + B_L_OFF + so, Bl + gb);
        }
    };

    // Prologue: stages 0..STAGES-2
    load_stage(0, 0); CP_COMMIT();
    load_stage(1, BKc); CP_COMMIT();

    float acc[2][8][4];
#pragma unroll
    for (int mi = 0; mi < 2; mi++)
#pragma unroll
        for (int ni = 0; ni < 8; ni++)
#pragma unroll
            for (int e = 0; e < 4; e++) acc[mi][ni][e] = 0.f;

    const int lrow = lane & 15;
    const int lchunk = (lane >> 4) * 16;   // byte offset of k-half

    for (int c = 0; c < nch; c++) {
        CP_WAIT1();
        __syncthreads();

        int cn = c + STAGES - 1;
        if (cn < nch) load_stage(cn % STAGES, cn * BKc);
        CP_COMMIT();

        const uint32_t sbase = sb + (c % STAGES) * STG_BYTES;
        const uint32_t sAh = sbase + A_H_OFF, sAl = sbase + A_L_OFF;
        const uint32_t sBh = sbase + B_H_OFF, sBl = sbase + B_L_OFF;

#pragma unroll
        for (int ks = 0; ks < 4; ks++) {
            const int kb = ks * 32 + lchunk;   // byte offset in 128B row
            uint32_t ah[2][4], al[2][4];
#pragma unroll
            for (int mi = 0; mi < 2; mi++) {
                uint32_t bo = sw128((uint32_t)((wm + mi * 16 + lrow) * 128 + kb));
                ldm4(ah[mi], sAh + bo);
                ldm4(al[mi], sAl + bo);
            }
            uint32_t bh[4][4], bl[4][4];
#pragma unroll
            for (int g = 0; g < 4; g++) {
                uint32_t bo = sw128((uint32_t)((wn + g * 16 + lrow) * 128 + kb));
                ldm4(bh[g], sBh + bo);
                ldm4(bl[g], sBl + bo);
            }
#pragma unroll
            for (int mi = 0; mi < 2; mi++)
#pragma unroll
                for (int ni = 0; ni < 8; ni++) {
                    int g = ni >> 1, hf = ni & 1;
                    mma16816(acc[mi][ni], ah[mi], bh[g][hf], bh[g][hf + 2]);
                    mma16816(acc[mi][ni], ah[mi], bl[g][hf], bl[g][hf + 2]);
                    mma16816(acc[mi][ni], al[mi], bh[g][hf], bh[g][hf + 2]);
                }
        }
    }

    // Epilogue: d0,d1 -> (row, col..col+1); d2,d3 -> (row+8, ...)
    const int gro = lane >> 2, thr = lane & 3;
#pragma unroll
    for (int mi = 0; mi < 2; mi++) {
        int r0 = rowBase + wm + mi * 16 + gro;
#pragma unroll
        for (int ni = 0; ni < 8; ni++) {
            int cb = colBase + wn + ni * 8 + thr * 2;
            float bx = bias[cb], by = bias[cb + 1];
            float2 o0, o1;
            o0.x = acc[mi][ni][0] + bx; o0.y = acc[mi][ni][1] + by;
            o1.x = acc[mi][ni][2] + bx; o1.y = acc[mi][ni][3] + by;
            *(float2*)(Cm + (size_t)r0 * N + cb) = o0;
            *(float2*)(Cm + (size_t)(r0 + 8) * N + cb) = o1;
        }
    }
}

// ---------------------------------------------------------------------------
// RoPE in-place on q and k slices of g_qkv (fp32)
// ---------------------------------------------------------------------------
__global__ void rope_kernel(float* __restrict__ qkv)
{
    const size_t NP = (size_t)B_ * T_ * (C_ / 2);
    size_t idx = (size_t)blockIdx.x * blockDim.x + threadIdx.x;
    if (idx >= 2 * NP) return;
    int sel = (idx >= NP) ? 1 : 0;
    size_t r = sel ? (idx - NP) : idx;
    int p = (int)(r % (C_ / 2));
    size_t bt = r / (C_ / 2);
    int t = (int)(bt % T_);

    float e = (float)(2 * p) * (1.0f / (float)C_);
    float inv = expf(-9.210340371976184f * e);
    float ang = (float)t * inv;

    float kq = rintf(ang * 0.15915494309189535f);
    float rr = fmaf(-kq, 6.28318548202514648f, ang);
    rr = fmaf(-kq, -1.7484556000744083e-7f, rr);
    float s, c;
    sincosf(rr, &s, &c);

    float* ptr = qkv + bt * (size_t)THREE_C + (size_t)sel * C_ + 2 * p;
    float2 v = *(float2*)ptr;
    float2 o;
    o.x = v.x * c - v.y * s;
    o.y = v.x * s + v.y * c;
    *(float2*)ptr = o;
}

// ---------------------------------------------------------------------------
// Flash attention, fp32, causal (unchanged from R7-passing version)
// ---------------------------------------------------------------------------
#define BQ 64
#define BKV 64
#define PAD 132
#define ATTN_SMEM_FLOATS (3 * BQ * PAD + BQ * BKV)

__global__ __launch_bounds__(256, 1)
void attn_kernel(const float* __restrict__ qkv, float* __restrict__ y)
{
    extern __shared__ float sm[];
    float* Qs = sm;
    float* Ks = Qs + BQ * PAD;
    float* Vs = Ks + BKV * PAD;
    float* Ps = Vs + BKV * PAD;

    const int qt = blockIdx.x;
    const int h  = blockIdx.y;
    const int b  = blockIdx.z;
    const int q0 = qt * BQ;
    const int tid = threadIdx.x;
    const int sq = tid >> 4;
    const int sk = tid & 15;
    const float SCALE = 0.08838834764831845f;

    {
        int lane = tid & 31, rofs = tid >> 5;
#pragma unroll
        for (int it = 0; it < 8; it++) {
            int row = rofs + it * 8;
            size_t g = ((size_t)(b * T_ + q0 + row)) * THREE_C + h * DH + lane * 4;
            float4 v = *(const float4*)(qkv + g);
            float* dst = &Qs[row * PAD + lane * 4];
            dst[0] = v.x * SCALE; dst[1] = v.y * SCALE;
            dst[2] = v.z * SCALE; dst[3] = v.w * SCALE;
        }
    }

    float m[4], l[4], O[4][8];
#pragma unroll
    for (int i = 0; i < 4; i++) {
        m[i] = -INFINITY; l[i] = 0.f;
#pragma unroll
        for (int j = 0; j < 8; j++) O[i][j] = 0.f;
    }

    for (int jt = 0; jt <= qt; jt++) {
        const int k0 = jt * BKV;
        __syncthreads();
        {
            int lane = tid & 31, rofs = tid >> 5;
#pragma unroll
            for (int it = 0; it < 8; it++) {
                int row = rofs + it * 8;
                size_t gk = ((size_t)(b * T_ + k0 + row)) * THREE_C + C_ + h * DH + lane * 4;
                *(float4*)&Ks[row * PAD + lane * 4] = *(const float4*)(qkv + gk);
                *(float4*)&Vs[row * PAD + lane * 4] = *(const float4*)(qkv + gk + C_);
            }
        }
        __syncthreads();

        float Sv[4][4];
#pragma unroll
        for (int i = 0; i < 4; i++)
#pragma unroll
            for (int j = 0; j < 4; j++) Sv[i][j] = 0.f;

#pragma unroll 8
        for (int dd = 0; dd < DH; dd += 4) {
            float4 q4[4], k4[4];
#pragma unroll
            for (int i = 0; i < 4; i++)
                q4[i] = *(const float4*)&Qs[(sq * 4 + i) * PAD + dd];
#pragma unroll
            for (int j = 0; j < 4; j++)
                k4[j] = *(const float4*)&Ks[(sk + 16 * j) * PAD + dd];
#pragma unroll
            for (int i = 0; i < 4; i++)
#pragma unroll
                for (int j = 0; j < 4; j++) {
                    Sv[i][j] = fmaf(q4[i].x, k4[j].x, Sv[i][j]);
                    Sv[i][j] = fmaf(q4[i].y, k4[j].y, Sv[i][j]);
                    Sv[i][j] = fmaf(q4[i].z, k4[j].z, Sv[i][j]);
                    Sv[i][j] = fmaf(q4[i].w, k4[j].w, Sv[i][j]);
                }
        }

        if (jt == qt) {
#pragma unroll
            for (int i = 0; i < 4; i++) {
                int qg = sq * 4 + i;
#pragma unroll
                for (int j = 0; j < 4; j++)
                    if (sk + 16 * j > qg) Sv[i][j] = -INFINITY;
            }
        }

#pragma unroll
        for (int i = 0; i < 4; i++) {
            float mt = fmaxf(fmaxf(Sv[i][0], Sv[i][1]), fmaxf(Sv[i][2], Sv[i][3]));
#pragma unroll
            for (int o = 8; o >= 1; o >>= 1)
                mt = fmaxf(mt, __shfl_xor_sync(0xffffffffu, mt, o));
            float mn = fmaxf(m[i], mt);
            float corr = expf(m[i] - mn);
            float ps[4], rs = 0.f;
#pragma unroll
            for (int j = 0; j < 4; j++) {
                ps[j] = expf(Sv[i][j] - mn);
                rs += ps[j];
            }
#pragma unroll
            for (int o = 8; o >= 1; o >>= 1)
                rs += __shfl_xor_sync(0xffffffffu, rs, o);
            l[i] = l[i] * corr + rs;
            m[i] = mn;
#pragma unroll
            for (int j = 0; j < 8; j++) O[i][j] *= corr;
#pragma unroll
            for (int j = 0; j < 4; j++)
                Ps[(sq * 4 + i) * BKV + sk + 16 * j] = ps[j];
        }
        __syncthreads();

#pragma unroll 2
        for (int kk = 0; kk < BKV; kk += 4) {
            float pr[4][4];
#pragma unroll
            for (int i = 0; i < 4; i++)
                *(float4*)pr[i] = *(const float4*)&Ps[(sq * 4 + i) * BKV + kk];
#pragma unroll
            for (int t4 = 0; t4 < 4; t4++) {
                float4 va = *(const float4*)&Vs[(kk + t4) * PAD + sk * 4];
                float4 vb = *(const float4*)&Vs[(kk + t4) * PAD + 64 + sk * 4];
#pragma unroll
                for (int i = 0; i < 4; i++) {
                    float p = pr[i][t4];
                    O[i][0] = fmaf(p, va.x, O[i][0]);
                    O[i][1] = fmaf(p, va.y, O[i][1]);
                    O[i][2] = fmaf(p, va.z, O[i][2]);
                    O[i][3] = fmaf(p, va.w, O[i][3]);
                    O[i][4] = fmaf(p, vb.x, O[i][4]);
                    O[i][5] = fmaf(p, vb.y, O[i][5]);
                    O[i][6] = fmaf(p, vb.z, O[i][6]);
                    O[i][7] = fmaf(p, vb.w, O[i][7]);
                }
            }
        }
    }

#pragma unroll
    for (int i = 0; i < 4; i++) {
        float inv_l = 1.f / l[i];
        size_t g = ((size_t)(b * T_ + q0 + sq * 4 + i)) * C_ + h * DH;
        float4 o0, o1;
        o0.x = O[i][0] * inv_l; o0.y = O[i][1] * inv_l;
        o0.z = O[i][2] * inv_l; o0.w = O[i][3] * inv_l;
        o1.x = O[i][4] * inv_l; o1.y = O[i][5] * inv_l;
        o1.z = O[i][6] * inv_l; o1.w = O[i][7] * inv_l;
        *(float4*)(y + g + sk * 4) = o0;
        *(float4*)(y + g + 64 + sk * 4) = o1;
    }
}

// ---------------------------------------------------------------------------
// Launch
// ---------------------------------------------------------------------------
extern "C" void kernel_launch(void* const* d_in, const int* in_sizes, int n_in,
                              void* d_out, int out_size)
{
    (void)in_sizes; (void)n_in; (void)out_size;
    const float* x      = (const float*)d_in[0];
    const float* w_qkv  = (const float*)d_in[1];
    const float* b_qkv  = (const float*)d_in[2];
    const float* w_proj = (const float*)d_in[3];
    const float* b_proj = (const float*)d_in[4];
    float* out = (float*)d_out;

    void *p_qkv, *p_y, *p_xh, *p_xl, *p_yh, *p_yl, *p_wqh, *p_wql, *p_wph, *p_wpl;
    cudaGetSymbolAddress(&p_qkv, g_qkv);
    cudaGetSymbolAddress(&p_y, g_y);
    cudaGetSymbolAddress(&p_xh, g_xc_h);
    cudaGetSymbolAddress(&p_xl, g_xc_l);
    cudaGetSymbolAddress(&p_yh, g_yc_h);
    cudaGetSymbolAddress(&p_yl, g_yc_l);
    cudaGetSymbolAddress(&p_wqh, g_wq_h);
    cudaGetSymbolAddress(&p_wql, g_wq_l);
    cudaGetSymbolAddress(&p_wph, g_wp_h);
    cudaGetSymbolAddress(&p_wpl, g_wp_l);

    float* qkv = (float*)p_qkv;
    float* y   = (float*)p_y;

    cudaFuncSetAttribute(gemm_hmma_bf16x3,
                         cudaFuncAttributeMaxDynamicSharedMemorySize, GEMM_DSM);

    // 0) Weight transpose+split and x split
    wconv<<<dim3(THREE_C / 32, C_ / 32), dim3(32, 8)>>>(
        w_qkv, (__nv_bfloat16*)p_wqh, (__nv_bfloat16*)p_wql, C_, THREE_C);
    wconv<<<dim3(C_ / 32, C_ / 32), dim3(32, 8)>>>(
        w_proj, (__nv_bfloat16*)p_wph, (__nv_bfloat16*)p_wpl, C_, C_);
    {
        long n8 = (long)M_ * C_ / 8;
        convert_hilo<<<(int)((n8 + 255) / 256), 256>>>(
            x, (__nv_bfloat16*)p_xh, (__nv_bfloat16*)p_xl, n8);
    }

    // 1) QKV = x @ w_qkv + b_qkv  (HMMA bf16x3)
    gemm_hmma_bf16x3<<<dim3(THREE_C / 128, M_ / 128), GEMM_THREADS, GEMM_DSM>>>(
        (const __nv_bfloat16*)p_xh, (const __nv_bfloat16*)p_xl,
        (const __nv_bfloat16*)p_wqh, (const __nv_bfloat16*)p_wql,
        b_qkv, qkv, THREE_C, C_);

    // 2) RoPE in-place
    {
        size_t total = 2ull * B_ * T_ * (C_ / 2);
        rope_kernel<<<(int)((total + 255) / 256), 256>>>(qkv);
    }

    // 3) Causal flash attention -> y
    {
        size_t smem = ATTN_SMEM_FLOATS * sizeof(float);
        cudaFuncSetAttribute(attn_kernel, cudaFuncAttributeMaxDynamicSharedMemorySize,
                             (int)smem);
        dim3 grid(T_ / BQ, H_, B_);
        attn_kernel<<<grid, 256, smem>>>(qkv, y);
    }

    // 4) y split + out = y @ w_proj + b_proj (HMMA bf16x3)
    {
        long n8 = (long)M_ * C_ / 8;
        convert_hilo<<<(int)((n8 + 255) / 256), 256>>>(
            y, (__nv_bfloat16*)p_yh, (__nv_bfloat16*)p_yl, n8);
    }
    gemm_hmma_bf16x3<<<dim3(C_ / 128, M_ / 128), GEMM_THREADS, GEMM_DSM>>>(
        (const __nv_bfloat16*)p_yh, (const __nv_bfloat16*)p_yl,
        (const __nv_bfloat16*)p_wph, (const __nv_bfloat16*)p_wpl,
        b_proj, out, C_, C_);
}

// round 10
// speedup vs baseline: 2.5350x; 1.3840x over previous
#include <cuda_runtime.h>
#include <cuda_bf16.h>
#include <math.h>
#include <stdint.h>

// Problem constants
#define B_ 4
#define T_ 2048
#define C_ 2048
#define H_ 16
#define DH 128
#define THREE_C (3 * C_)
#define M_ (B_ * T_)   // 8192

// ---------------------------------------------------------------------------
// Device-global scratch (allocation-free)
// ---------------------------------------------------------------------------
__device__ float g_qkv[(size_t)B_ * T_ * THREE_C];          // 192 MiB
__device__ float g_y[(size_t)B_ * T_ * C_];                 // 64 MiB
__device__ __nv_bfloat16 g_xc_h[(size_t)M_ * C_];
__device__ __nv_bfloat16 g_xc_l[(size_t)M_ * C_];
__device__ __nv_bfloat16 g_yc_h[(size_t)M_ * C_];
__device__ __nv_bfloat16 g_yc_l[(size_t)M_ * C_];
__device__ __nv_bfloat16 g_wq_h[(size_t)THREE_C * C_];      // w_qkv^T [6144,2048]
__device__ __nv_bfloat16 g_wq_l[(size_t)THREE_C * C_];
__device__ __nv_bfloat16 g_wp_h[(size_t)C_ * C_];           // w_proj^T [2048,2048]
__device__ __nv_bfloat16 g_wp_l[(size_t)C_ * C_];

// ---------------------------------------------------------------------------
// Helpers
// ---------------------------------------------------------------------------
__device__ __forceinline__ uint32_t smem_u32(const void* p) {
    uint32_t a;
    asm("{ .reg .u64 t; cvta.to.shared.u64 t, %1; cvt.u32.u64 %0, t; }"
        : "=r"(a) : "l"(p));
    return a;
}
static __device__ __forceinline__ uint32_t sw128(uint32_t x) {
    return x ^ ((x >> 3) & 0x70);
}
__device__ __forceinline__ void cpa16(uint32_t s, const void* g) {
    asm volatile("cp.async.cg.shared.global [%0], [%1], 16;" :: "r"(s), "l"(g));
}
#define CP_COMMIT() asm volatile("cp.async.commit_group;" ::: "memory")
#define CP_WAIT1()  asm volatile("cp.async.wait_group 1;" ::: "memory")

__device__ __forceinline__ void ldm4(uint32_t* r, uint32_t addr) {
    asm volatile("ldmatrix.sync.aligned.m8n8.x4.shared.b16 {%0,%1,%2,%3}, [%4];"
                 : "=r"(r[0]), "=r"(r[1]), "=r"(r[2]), "=r"(r[3]) : "r"(addr));
}
__device__ __forceinline__ void ldm4t(uint32_t* r, uint32_t addr) {
    asm volatile("ldmatrix.sync.aligned.m8n8.x4.trans.shared.b16 {%0,%1,%2,%3}, [%4];"
                 : "=r"(r[0]), "=r"(r[1]), "=r"(r[2]), "=r"(r[3]) : "r"(addr));
}
__device__ __forceinline__ void mma16816(float* d, const uint32_t* a,
                                         uint32_t b0, uint32_t b1) {
    asm volatile(
        "mma.sync.aligned.m16n8k16.row.col.f32.bf16.bf16.f32 "
        "{%0,%1,%2,%3}, {%4,%5,%6,%7}, {%8,%9}, {%0,%1,%2,%3};"
        : "+f"(d[0]), "+f"(d[1]), "+f"(d[2]), "+f"(d[3])
        : "r"(a[0]), "r"(a[1]), "r"(a[2]), "r"(a[3]), "r"(b0), "r"(b1));
}
__device__ __forceinline__ uint32_t packbf(float a, float b) {
    __nv_bfloat162 t = __floats2bfloat162_rn(a, b);   // .x = a (low 16 bits)
    return *(uint32_t*)&t;
}

// ---------------------------------------------------------------------------
// Elementwise fp32 -> bf16 (hi, lo) split. n8 = elements/8.
// ---------------------------------------------------------------------------
__global__ void convert_hilo(const float* __restrict__ X,
                             __nv_bfloat16* __restrict__ Hh,
                             __nv_bfloat16* __restrict__ Hl, long n8)
{
    long i = (long)blockIdx.x * blockDim.x + threadIdx.x;
    if (i >= n8) return;
    float4 a = ((const float4*)X)[i * 2 + 0];
    float4 b = ((const float4*)X)[i * 2 + 1];
    float v[8] = {a.x, a.y, a.z, a.w, b.x, b.y, b.z, b.w};
    union { __nv_bfloat16 e[8]; uint4 u; } ph, pl;
#pragma unroll
    for (int j = 0; j < 8; j++) {
        __nv_bfloat16 h = __float2bfloat16(v[j]);
        ph.e[j] = h;
        pl.e[j] = __float2bfloat16(v[j] - __bfloat162float(h));
    }
    ((uint4*)Hh)[i] = ph.u;
    ((uint4*)Hl)[i] = pl.u;
}

// ---------------------------------------------------------------------------
// Transpose + split: W[K,N] fp32 row-major -> Th/Tl [N,K] bf16 row-major
// ---------------------------------------------------------------------------
__global__ void wconv(const float* __restrict__ W, __nv_bfloat16* __restrict__ Th,
                      __nv_bfloat16* __restrict__ Tl, int K, int N)
{
    __shared__ float ts[32][33];
    int n0 = blockIdx.x * 32, k0 = blockIdx.y * 32;
    int tx = threadIdx.x, ty = threadIdx.y;
    for (int i = ty; i < 32; i += 8)
        ts[i][tx] = W[(size_t)(k0 + i) * N + n0 + tx];
    __syncthreads();
    for (int i = ty; i < 32; i += 8) {
        float v = ts[tx][i];
        __nv_bfloat16 h = __float2bfloat16(v);
        __nv_bfloat16 l = __float2bfloat16(v - __bfloat162float(h));
        size_t o = (size_t)(n0 + i) * K + k0 + tx;
        Th[o] = h;
        Tl[o] = l;
    }
}

// ---------------------------------------------------------------------------
// HMMA bf16x3 GEMM (unchanged from R9-passing version)
// ---------------------------------------------------------------------------
#define GEMM_THREADS 256
#define BKc 64
#define A_H_OFF 0
#define A_L_OFF 16384
#define B_H_OFF 32768
#define B_L_OFF 49152
#define STG_BYTES 65536
#define STAGES 3
#define GEMM_DSM (STAGES * STG_BYTES + 1024)

__global__ __launch_bounds__(GEMM_THREADS, 1)
void gemm_hmma_bf16x3(const __nv_bfloat16* __restrict__ Ah,
                      const __nv_bfloat16* __restrict__ Al,
                      const __nv_bfloat16* __restrict__ Bh,
                      const __nv_bfloat16* __restrict__ Bl,
                      const float* __restrict__ bias, float* __restrict__ Cm,
                      int N, int K)
{
    extern __shared__ char dsm[];
    const uint32_t raw = smem_u32(dsm);
    const uint32_t sb = (raw + 1023u) & ~1023u;

    const int tid = threadIdx.x;
    const int wid = tid >> 5, lane = tid & 31;
    const int wm = (wid & 3) * 32;
    const int wn = (wid >> 2) * 64;
    const int rowBase = blockIdx.y * 128;
    const int colBase = blockIdx.x * 128;
    const int nch = K / BKc;

    auto load_stage = [&](int st, int k0) {
        uint32_t sbase = sb + st * STG_BYTES;
#pragma unroll
        for (int rep = 0; rep < 4; rep++) {
            int i = tid + rep * GEMM_THREADS;
            int row = i >> 3, cc = i & 7;
            uint32_t so = sw128((uint32_t)(row * 128 + cc * 16));
            size_t ga = (size_t)(rowBase + row) * K + k0 + cc * 8;
            size_t gb = (size_t)(colBase + row) * K + k0 + cc * 8;
            cpa16(sbase + A_H_OFF + so, Ah + ga);
            cpa16(sbase + A_L_OFF + so, Al + ga);
            cpa16(sbase + B_H_OFF + so, Bh + gb);
            cpa16(sbase + B_L_OFF + so, Bl + gb);
        }
    };

    load_stage(0, 0); CP_COMMIT();
    load_stage(1, BKc); CP_COMMIT();

    float acc[2][8][4];
#pragma unroll
    for (int mi = 0; mi < 2; mi++)
#pragma unroll
        for (int ni = 0; ni < 8; ni++)
#pragma unroll
            for (int e = 0; e < 4; e++) acc[mi][ni][e] = 0.f;

    const int lrow = lane & 15;
    const int lchunk = (lane >> 4) * 16;

    for (int c = 0; c < nch; c++) {
        CP_WAIT1();
        __syncthreads();

        int cn = c + STAGES - 1;
        if (cn < nch) load_stage(cn % STAGES, cn * BKc);
        CP_COMMIT();

        const uint32_t sbase = sb + (c % STAGES) * STG_BYTES;
        const uint32_t sAh = sbase + A_H_OFF, sAl = sbase + A_L_OFF;
        const uint32_t sBh = sbase + B_H_OFF, sBl = sbase + B_L_OFF;

#pragma unroll
        for (int ks = 0; ks < 4; ks++) {
            const int kb = ks * 32 + lchunk;
            uint32_t ah[2][4], al[2][4];
#pragma unroll
            for (int mi = 0; mi < 2; mi++) {
                uint32_t bo = sw128((uint32_t)((wm + mi * 16 + lrow) * 128 + kb));
                ldm4(ah[mi], sAh + bo);
                ldm4(al[mi], sAl + bo);
            }
            uint32_t bh[4][4], bl[4][4];
#pragma unroll
            for (int g = 0; g < 4; g++) {
                uint32_t bo = sw128((uint32_t)((wn + g * 16 + lrow) * 128 + kb));
                ldm4(bh[g], sBh + bo);
                ldm4(bl[g], sBl + bo);
            }
#pragma unroll
            for (int mi = 0; mi < 2; mi++)
#pragma unroll
                for (int ni = 0; ni < 8; ni++) {
                    int g = ni >> 1, hf = ni & 1;
                    mma16816(acc[mi][ni], ah[mi], bh[g][hf], bh[g][hf + 2]);
                    mma16816(acc[mi][ni], ah[mi], bl[g][hf], bl[g][hf + 2]);
                    mma16816(acc[mi][ni], al[mi], bh[g][hf], bh[g][hf + 2]);
                }
        }
    }

    const int gro = lane >> 2, thr = lane & 3;
#pragma unroll
    for (int mi = 0; mi < 2; mi++) {
        int r0 = rowBase + wm + mi * 16 + gro;
#pragma unroll
        for (int ni = 0; ni < 8; ni++) {
            int cb = colBase + wn + ni * 8 + thr * 2;
            float bx = bias[cb], by = bias[cb + 1];
            float2 o0, o1;
            o0.x = acc[mi][ni][0] + bx; o0.y = acc[mi][ni][1] + by;
            o1.x = acc[mi][ni][2] + bx; o1.y = acc[mi][ni][3] + by;
            *(float2*)(Cm + (size_t)r0 * N + cb) = o0;
            *(float2*)(Cm + (size_t)(r0 + 8) * N + cb) = o1;
        }
    }
}

// ---------------------------------------------------------------------------
// RoPE in-place on q and k slices of g_qkv (fp32)
// ---------------------------------------------------------------------------
__global__ void rope_kernel(float* __restrict__ qkv)
{
    const size_t NP = (size_t)B_ * T_ * (C_ / 2);
    size_t idx = (size_t)blockIdx.x * blockDim.x + threadIdx.x;
    if (idx >= 2 * NP) return;
    int sel = (idx >= NP) ? 1 : 0;
    size_t r = sel ? (idx - NP) : idx;
    int p = (int)(r % (C_ / 2));
    size_t bt = r / (C_ / 2);
    int t = (int)(bt % T_);

    float e = (float)(2 * p) * (1.0f / (float)C_);
    float inv = expf(-9.210340371976184f * e);
    float ang = (float)t * inv;

    float kq = rintf(ang * 0.15915494309189535f);
    float rr = fmaf(-kq, 6.28318548202514648f, ang);
    rr = fmaf(-kq, -1.7484556000744083e-7f, rr);
    float s, c;
    sincosf(rr, &s, &c);

    float* ptr = qkv + bt * (size_t)THREE_C + (size_t)sel * C_ + 2 * p;
    float2 v = *(float2*)ptr;
    float2 o;
    o.x = v.x * c - v.y * s;
    o.y = v.x * s + v.y * c;
    *(float2*)ptr = o;
}

// ---------------------------------------------------------------------------
// HMMA flash attention, causal, bf16x3 (hi/lo) for QK^T and P*V.
// CTA = (b, h, 128-row q tile). 256 threads, 8 warps x 16 q rows.
// SMEM: Q hi/lo [128][128]bf16, K hi/lo [64][128], V hi/lo [64][128],
// 256B rows with XOR swizzle (byte ^ ((row&7)<<4)).
// ---------------------------------------------------------------------------
#define AQH 0
#define AQL 32768
#define AKH 65536
#define AKL 81920
#define AVH 98304
#define AVL 114688
#define ATTN2_DSM (131072 + 1024)

__global__ __launch_bounds__(256, 1)
void attn_hmma(const float* __restrict__ qkv, float* __restrict__ y)
{
    extern __shared__ char asmem[];
    const uint32_t raw = smem_u32(asmem);
    const uint32_t sb = (raw + 1023u) & ~1023u;
    char* sbp = asmem + (sb - raw);

    const int qt = blockIdx.x, h = blockIdx.y, b = blockIdx.z;
    const int qb = qt * 128;
    const int tid = threadIdx.x;
    const int wid = tid >> 5, lane = tid & 31;
    const int wq0 = wid * 16;              // warp's q-row offset in tile
    const int lrow = lane & 15;
    const int lch = (lane >> 4) * 16;      // 16B chunk select for ldm4
    const int gro = lane >> 2, thr = lane & 3;
    const uint32_t rx = ((uint32_t)(lrow & 7)) << 4;   // swizzle for ldm4 rows
    const float SCALE = 0.08838834764831845f;          // 1/sqrt(128)

    // ---- Load Q tile: fp32 -> scaled bf16 hi/lo, swizzled ----
#pragma unroll
    for (int rep = 0; rep < 16; rep++) {
        int idx = tid + rep * 256;
        int row = idx >> 5, jc = idx & 31;
        size_t g = ((size_t)(b * T_ + qb + row)) * THREE_C + h * DH + jc * 4;
        float4 v = *(const float4*)(qkv + g);
        v.x *= SCALE; v.y *= SCALE; v.z *= SCALE; v.w *= SCALE;
        __nv_bfloat16 h0 = __float2bfloat16(v.x), h1 = __float2bfloat16(v.y);
        __nv_bfloat16 h2 = __float2bfloat16(v.z), h3 = __float2bfloat16(v.w);
        uint2 uh, ul;
        uh.x = packbf(v.x, v.y); uh.y = packbf(v.z, v.w);
        ul.x = packbf(v.x - __bfloat162float(h0), v.y - __bfloat162float(h1));
        ul.y = packbf(v.z - __bfloat162float(h2), v.w - __bfloat162float(h3));
        uint32_t off = (uint32_t)row * 256 +
                       (((uint32_t)(jc * 8)) ^ (((uint32_t)(row & 7)) << 4));
        *(uint2*)(sbp + AQH + off) = uh;
        *(uint2*)(sbp + AQL + off) = ul;
    }

    float m0 = -INFINITY, m1 = -INFINITY, l0 = 0.f, l1 = 0.f;
    float O[16][4];
#pragma unroll
    for (int i = 0; i < 16; i++)
#pragma unroll
        for (int e = 0; e < 4; e++) O[i][e] = 0.f;

    const int ntiles = 2 * qt + 2;
    for (int j = 0; j < ntiles; j++) {
        const int kvg = j * 64;
        __syncthreads();   // prior iteration done reading K/V (and Q loaded)

        // ---- Load K,V tiles: fp32 -> bf16 hi/lo, swizzled ----
#pragma unroll
        for (int rep = 0; rep < 8; rep++) {
            int idx = tid + rep * 256;
            int row = idx >> 5, jc = idx & 31;
            size_t g = ((size_t)(b * T_ + kvg + row)) * THREE_C + C_ + h * DH + jc * 4;
            float4 kv = *(const float4*)(qkv + g);
            float4 vv = *(const float4*)(qkv + g + C_);
            uint32_t off = (uint32_t)row * 256 +
                           (((uint32_t)(jc * 8)) ^ (((uint32_t)(row & 7)) << 4));
            {
                __nv_bfloat16 h0 = __float2bfloat16(kv.x), h1 = __float2bfloat16(kv.y);
                __nv_bfloat16 h2 = __float2bfloat16(kv.z), h3 = __float2bfloat16(kv.w);
                uint2 uh, ul;
                uh.x = packbf(kv.x, kv.y); uh.y = packbf(kv.z, kv.w);
                ul.x = packbf(kv.x - __bfloat162float(h0), kv.y - __bfloat162float(h1));
                ul.y = packbf(kv.z - __bfloat162float(h2), kv.w - __bfloat162float(h3));
                *(uint2*)(sbp + AKH + off) = uh;
                *(uint2*)(sbp + AKL + off) = ul;
            }
            {
                __nv_bfloat16 h0 = __float2bfloat16(vv.x), h1 = __float2bfloat16(vv.y);
                __nv_bfloat16 h2 = __float2bfloat16(vv.z), h3 = __float2bfloat16(vv.w);
                uint2 uh, ul;
                uh.x = packbf(vv.x, vv.y); uh.y = packbf(vv.z, vv.w);
                ul.x = packbf(vv.x - __bfloat162float(h0), vv.y - __bfloat162float(h1));
                ul.y = packbf(vv.z - __bfloat162float(h2), vv.w - __bfloat162float(h3));
                *(uint2*)(sbp + AVH + off) = uh;
                *(uint2*)(sbp + AVL + off) = ul;
            }
        }
        __syncthreads();

        // ---- S = Q K^T (3-term bf16x3) ----
        float c[8][4];
#pragma unroll
        for (int nt = 0; nt < 8; nt++)
#pragma unroll
            for (int e = 0; e < 4; e++) c[nt][e] = 0.f;

#pragma unroll
        for (int kc = 0; kc < 8; kc++) {
            const uint32_t kb = (uint32_t)(kc * 32 + lch);
            uint32_t aqh[4], aql[4];
            {
                uint32_t off = (uint32_t)(wq0 + lrow) * 256 + (kb ^ rx);
                ldm4(aqh, sb + AQH + off);
                ldm4(aql, sb + AQL + off);
            }
#pragma unroll
            for (int g4 = 0; g4 < 4; g4++) {
                uint32_t off = (uint32_t)(g4 * 16 + lrow) * 256 + (kb ^ rx);
                uint32_t bh[4], bl[4];
                ldm4(bh, sb + AKH + off);
                ldm4(bl, sb + AKL + off);
#pragma unroll
                for (int hf = 0; hf < 2; hf++) {
                    int nt = g4 * 2 + hf;
                    mma16816(c[nt], aqh, bh[hf], bh[hf + 2]);
                    mma16816(c[nt], aqh, bl[hf], bl[hf + 2]);
                    mma16816(c[nt], aql, bh[hf], bh[hf + 2]);
                }
            }
        }

        // ---- Causal mask ----
        const int row_lo = qb + wq0 + gro;
        const int row_hi = row_lo + 8;
        if (kvg + 63 > qb + wq0) {
#pragma unroll
            for (int nt = 0; nt < 8; nt++) {
                int cbase = kvg + nt * 8 + 2 * thr;
                if (cbase > row_lo)     c[nt][0] = -1e30f;
                if (cbase + 1 > row_lo) c[nt][1] = -1e30f;
                if (cbase > row_hi)     c[nt][2] = -1e30f;
                if (cbase + 1 > row_hi) c[nt][3] = -1e30f;
            }
        }

        // ---- Online softmax (rows gro and gro+8) ----
        float mt0 = -1e30f, mt1 = -1e30f;
#pragma unroll
        for (int nt = 0; nt < 8; nt++) {
            mt0 = fmaxf(mt0, fmaxf(c[nt][0], c[nt][1]));
            mt1 = fmaxf(mt1, fmaxf(c[nt][2], c[nt][3]));
        }
        mt0 = fmaxf(mt0, __shfl_xor_sync(0xffffffffu, mt0, 1));
        mt0 = fmaxf(mt0, __shfl_xor_sync(0xffffffffu, mt0, 2));
        mt1 = fmaxf(mt1, __shfl_xor_sync(0xffffffffu, mt1, 1));
        mt1 = fmaxf(mt1, __shfl_xor_sync(0xffffffffu, mt1, 2));
        float mn0 = fmaxf(m0, mt0), mn1 = fmaxf(m1, mt1);
        float cor0 = expf(m0 - mn0), cor1 = expf(m1 - mn1);
        float s0 = 0.f, s1 = 0.f;
#pragma unroll
        for (int nt = 0; nt < 8; nt++) {
            c[nt][0] = expf(c[nt][0] - mn0); s0 += c[nt][0];
            c[nt][1] = expf(c[nt][1] - mn0); s0 += c[nt][1];
            c[nt][2] = expf(c[nt][2] - mn1); s1 += c[nt][2];
            c[nt][3] = expf(c[nt][3] - mn1); s1 += c[nt][3];
        }
        s0 += __shfl_xor_sync(0xffffffffu, s0, 1);
        s0 += __shfl_xor_sync(0xffffffffu, s0, 2);
        s1 += __shfl_xor_sync(0xffffffffu, s1, 1);
        s1 += __shfl_xor_sync(0xffffffffu, s1, 2);
        l0 = l0 * cor0 + s0; m0 = mn0;
        l1 = l1 * cor1 + s1; m1 = mn1;
#pragma unroll
        for (int i = 0; i < 16; i++) {
            O[i][0] *= cor0; O[i][1] *= cor0;
            O[i][2] *= cor1; O[i][3] *= cor1;
        }

        // ---- O += P V (3-term; P hi/lo built in registers) ----
        const uint32_t rxv = ((uint32_t)(lane & 7)) << 4;
        const uint32_t colb = (uint32_t)((lane >> 3) & 1) * 16;
#pragma unroll
        for (int kc2 = 0; kc2 < 4; kc2++) {
            uint32_t aph[4], apl[4];
            {
                float p00 = c[2 * kc2][0], p01 = c[2 * kc2][1];
                float p10 = c[2 * kc2][2], p11 = c[2 * kc2][3];
                float p20 = c[2 * kc2 + 1][0], p21 = c[2 * kc2 + 1][1];
                float p30 = c[2 * kc2 + 1][2], p31 = c[2 * kc2 + 1][3];
                aph[0] = packbf(p00, p01);
                aph[1] = packbf(p10, p11);
                aph[2] = packbf(p20, p21);
                aph[3] = packbf(p30, p31);
                __nv_bfloat162* t;
                t = (__nv_bfloat162*)&aph[0];
                apl[0] = packbf(p00 - __bfloat162float(t->x), p01 - __bfloat162float(t->y));
                t = (__nv_bfloat162*)&aph[1];
                apl[1] = packbf(p10 - __bfloat162float(t->x), p11 - __bfloat162float(t->y));
                t = (__nv_bfloat162*)&aph[2];
                apl[2] = packbf(p20 - __bfloat162float(t->x), p21 - __bfloat162float(t->y));
                t = (__nv_bfloat162*)&aph[3];
                apl[3] = packbf(p30 - __bfloat162float(t->x), p31 - __bfloat162float(t->y));
            }
            const uint32_t vrow = (uint32_t)(kc2 * 16 + (lane & 7) + (lane >> 4) * 8);
#pragma unroll
            for (int gg = 0; gg < 8; gg++) {
                uint32_t off = vrow * 256 + (((uint32_t)(gg * 32) + colb) ^ rxv);
                uint32_t vh[4], vl[4];
                ldm4t(vh, sb + AVH + off);
                ldm4t(vl, sb + AVL + off);
#pragma unroll
                for (int hf = 0; hf < 2; hf++) {
                    int nt2 = gg * 2 + hf;
                    mma16816(O[nt2], aph, vh[hf], vh[hf + 2]);
                    mma16816(O[nt2], aph, vl[hf], vl[hf + 2]);
                    mma16816(O[nt2], apl, vh[hf], vh[hf + 2]);
                }
            }
        }
    }

    // ---- Epilogue: normalize and store y (B,T,C), c = h*128 + d ----
    const float il0 = 1.f / l0, il1 = 1.f / l1;
    const int row_lo = qb + wq0 + gro;
#pragma unroll
    for (int nt2 = 0; nt2 < 16; nt2++) {
        int col = h * DH + nt2 * 8 + 2 * thr;
        float2 o0, o1;
        o0.x = O[nt2][0] * il0; o0.y = O[nt2][1] * il0;
        o1.x = O[nt2][2] * il1; o1.y = O[nt2][3] * il1;
        *(float2*)(y + ((size_t)(b * T_ + row_lo)) * C_ + col) = o0;
        *(float2*)(y + ((size_t)(b * T_ + row_lo + 8)) * C_ + col) = o1;
    }
}

// ---------------------------------------------------------------------------
// Launch
// ---------------------------------------------------------------------------
extern "C" void kernel_launch(void* const* d_in, const int* in_sizes, int n_in,
                              void* d_out, int out_size)
{
    (void)in_sizes; (void)n_in; (void)out_size;
    const float* x      = (const float*)d_in[0];
    const float* w_qkv  = (const float*)d_in[1];
    const float* b_qkv  = (const float*)d_in[2];
    const float* w_proj = (const float*)d_in[3];
    const float* b_proj = (const float*)d_in[4];
    float* out = (float*)d_out;

    void *p_qkv, *p_y, *p_xh, *p_xl, *p_yh, *p_yl, *p_wqh, *p_wql, *p_wph, *p_wpl;
    cudaGetSymbolAddress(&p_qkv, g_qkv);
    cudaGetSymbolAddress(&p_y, g_y);
    cudaGetSymbolAddress(&p_xh, g_xc_h);
    cudaGetSymbolAddress(&p_xl, g_xc_l);
    cudaGetSymbolAddress(&p_yh, g_yc_h);
    cudaGetSymbolAddress(&p_yl, g_yc_l);
    cudaGetSymbolAddress(&p_wqh, g_wq_h);
    cudaGetSymbolAddress(&p_wql, g_wq_l);
    cudaGetSymbolAddress(&p_wph, g_wp_h);
    cudaGetSymbolAddress(&p_wpl, g_wp_l);

    float* qkv = (float*)p_qkv;
    float* y   = (float*)p_y;

    cudaFuncSetAttribute(gemm_hmma_bf16x3,
                         cudaFuncAttributeMaxDynamicSharedMemorySize, GEMM_DSM);
    cudaFuncSetAttribute(attn_hmma,
                         cudaFuncAttributeMaxDynamicSharedMemorySize, ATTN2_DSM);

    // 0) Weight transpose+split and x split
    wconv<<<dim3(THREE_C / 32, C_ / 32), dim3(32, 8)>>>(
        w_qkv, (__nv_bfloat16*)p_wqh, (__nv_bfloat16*)p_wql, C_, THREE_C);
    wconv<<<dim3(C_ / 32, C_ / 32), dim3(32, 8)>>>(
        w_proj, (__nv_bfloat16*)p_wph, (__nv_bfloat16*)p_wpl, C_, C_);
    {
        long n8 = (long)M_ * C_ / 8;
        convert_hilo<<<(int)((n8 + 255) / 256), 256>>>(
            x, (__nv_bfloat16*)p_xh, (__nv_bfloat16*)p_xl, n8);
    }

    // 1) QKV = x @ w_qkv + b_qkv  (HMMA bf16x3)
    gemm_hmma_bf16x3<<<dim3(THREE_C / 128, M_ / 128), GEMM_THREADS, GEMM_DSM>>>(
        (const __nv_bfloat16*)p_xh, (const __nv_bfloat16*)p_xl,
        (const __nv_bfloat16*)p_wqh, (const __nv_bfloat16*)p_wql,
        b_qkv, qkv, THREE_C, C_);

    // 2) RoPE in-place
    {
        size_t total = 2ull * B_ * T_ * (C_ / 2);
        rope_kernel<<<(int)((total + 255) / 256), 256>>>(qkv);
    }

    // 3) Causal flash attention (HMMA bf16x3) -> y
    {
        dim3 grid(T_ / 128, H_, B_);
        attn_hmma<<<grid, 256, ATTN2_DSM>>>(qkv, y);
    }

    // 4) y split + out = y @ w_proj + b_proj (HMMA bf16x3)
    {
        long n8 = (long)M_ * C_ / 8;
        convert_hilo<<<(int)((n8 + 255) / 256), 256>>>(
            y, (__nv_bfloat16*)p_yh, (__nv_bfloat16*)p_yl, n8);
    }
    gemm_hmma_bf16x3<<<dim3(C_ / 128, M_ / 128), GEMM_THREADS, GEMM_DSM>>>(
        (const __nv_bfloat16*)p_yh, (const __nv_bfloat16*)p_yl,
        (const __nv_bfloat16*)p_wph, (const __nv_bfloat16*)p_wpl,
        b_proj, out, C_, C_);
}

// round 11
// speedup vs baseline: 2.5918x; 1.0224x over previous
#include <cuda_runtime.h>
#include <cuda_bf16.h>
#include <math.h>
#include <stdint.h>

// Problem constants
#define B_ 4
#define T_ 2048
#define C_ 2048
#define H_ 16
#define DH 128
#define THREE_C (3 * C_)
#define M_ (B_ * T_)   // 8192

// ---------------------------------------------------------------------------
// Device-global scratch (allocation-free)
// ---------------------------------------------------------------------------
__device__ __nv_bfloat16 g_xc_h[(size_t)M_ * C_];
__device__ __nv_bfloat16 g_xc_l[(size_t)M_ * C_];
__device__ __nv_bfloat16 g_yc_h[(size_t)M_ * C_];
__device__ __nv_bfloat16 g_yc_l[(size_t)M_ * C_];
__device__ __nv_bfloat16 g_wq_h[(size_t)THREE_C * C_];      // w_qkv^T [6144,2048]
__device__ __nv_bfloat16 g_wq_l[(size_t)THREE_C * C_];
__device__ __nv_bfloat16 g_wp_h[(size_t)C_ * C_];           // w_proj^T [2048,2048]
__device__ __nv_bfloat16 g_wp_l[(size_t)C_ * C_];
// Roped/scaled bf16 hi/lo Q,K and split V, layout [M_][C_] (c = h*128+d)
__device__ __nv_bfloat16 g_qh[(size_t)M_ * C_];
__device__ __nv_bfloat16 g_ql[(size_t)M_ * C_];
__device__ __nv_bfloat16 g_kh[(size_t)M_ * C_];
__device__ __nv_bfloat16 g_kl[(size_t)M_ * C_];
__device__ __nv_bfloat16 g_vh[(size_t)M_ * C_];
__device__ __nv_bfloat16 g_vl[(size_t)M_ * C_];

// ---------------------------------------------------------------------------
// Helpers
// ---------------------------------------------------------------------------
__device__ __forceinline__ uint32_t smem_u32(const void* p) {
    uint32_t a;
    asm("{ .reg .u64 t; cvta.to.shared.u64 t, %1; cvt.u32.u64 %0, t; }"
        : "=r"(a) : "l"(p));
    return a;
}
static __device__ __forceinline__ uint32_t sw128(uint32_t x) {
    return x ^ ((x >> 3) & 0x70);
}
__device__ __forceinline__ void cpa16(uint32_t s, const void* g) {
    asm volatile("cp.async.cg.shared.global [%0], [%1], 16;" :: "r"(s), "l"(g));
}
#define CP_COMMIT() asm volatile("cp.async.commit_group;" ::: "memory")
#define CP_WAIT1()  asm volatile("cp.async.wait_group 1;" ::: "memory")
#define CP_WAIT0()  asm volatile("cp.async.wait_group 0;" ::: "memory")

__device__ __forceinline__ void ldm4(uint32_t* r, uint32_t addr) {
    asm volatile("ldmatrix.sync.aligned.m8n8.x4.shared.b16 {%0,%1,%2,%3}, [%4];"
                 : "=r"(r[0]), "=r"(r[1]), "=r"(r[2]), "=r"(r[3]) : "r"(addr));
}
__device__ __forceinline__ void ldm4t(uint32_t* r, uint32_t addr) {
    asm volatile("ldmatrix.sync.aligned.m8n8.x4.trans.shared.b16 {%0,%1,%2,%3}, [%4];"
                 : "=r"(r[0]), "=r"(r[1]), "=r"(r[2]), "=r"(r[3]) : "r"(addr));
}
__device__ __forceinline__ void mma16816(float* d, const uint32_t* a,
                                         uint32_t b0, uint32_t b1) {
    asm volatile(
        "mma.sync.aligned.m16n8k16.row.col.f32.bf16.bf16.f32 "
        "{%0,%1,%2,%3}, {%4,%5,%6,%7}, {%8,%9}, {%0,%1,%2,%3};"
        : "+f"(d[0]), "+f"(d[1]), "+f"(d[2]), "+f"(d[3])
        : "r"(a[0]), "r"(a[1]), "r"(a[2]), "r"(a[3]), "r"(b0), "r"(b1));
}
__device__ __forceinline__ uint32_t packbf(float a, float b) {
    __nv_bfloat162 t = __floats2bfloat162_rn(a, b);   // .x = a (low 16 bits)
    return *(uint32_t*)&t;
}
__device__ __forceinline__ float ex2f(float x) {
    float r;
    asm("ex2.approx.f32 %0, %1;" : "=f"(r) : "f"(x));
    return r;
}

// ---------------------------------------------------------------------------
// Elementwise fp32 -> bf16 (hi, lo) split. n8 = elements/8.
// ---------------------------------------------------------------------------
__global__ void convert_hilo(const float* __restrict__ X,
                             __nv_bfloat16* __restrict__ Hh,
                             __nv_bfloat16* __restrict__ Hl, long n8)
{
    long i = (long)blockIdx.x * blockDim.x + threadIdx.x;
    if (i >= n8) return;
    float4 a = ((const float4*)X)[i * 2 + 0];
    float4 b = ((const float4*)X)[i * 2 + 1];
    float v[8] = {a.x, a.y, a.z, a.w, b.x, b.y, b.z, b.w};
    union { __nv_bfloat16 e[8]; uint4 u; } ph, pl;
#pragma unroll
    for (int j = 0; j < 8; j++) {
        __nv_bfloat16 h = __float2bfloat16(v[j]);
        ph.e[j] = h;
        pl.e[j] = __float2bfloat16(v[j] - __bfloat162float(h));
    }
    ((uint4*)Hh)[i] = ph.u;
    ((uint4*)Hl)[i] = pl.u;
}

// ---------------------------------------------------------------------------
// Transpose + split: W[K,N] fp32 row-major -> Th/Tl [N,K] bf16 row-major
// ---------------------------------------------------------------------------
__global__ void wconv(const float* __restrict__ W, __nv_bfloat16* __restrict__ Th,
                      __nv_bfloat16* __restrict__ Tl, int K, int N)
{
    __shared__ float ts[32][33];
    int n0 = blockIdx.x * 32, k0 = blockIdx.y * 32;
    int tx = threadIdx.x, ty = threadIdx.y;
    for (int i = ty; i < 32; i += 8)
        ts[i][tx] = W[(size_t)(k0 + i) * N + n0 + tx];
    __syncthreads();
    for (int i = ty; i < 32; i += 8) {
        float v = ts[tx][i];
        __nv_bfloat16 h = __float2bfloat16(v);
        __nv_bfloat16 l = __float2bfloat16(v - __bfloat162float(h));
        size_t o = (size_t)(n0 + i) * K + k0 + tx;
        Th[o] = h;
        Tl[o] = l;
    }
}

// ---------------------------------------------------------------------------
// Shared GEMM config (CTA 128x128, BK=64, 3-stage cp.async, 256 thr)
// ---------------------------------------------------------------------------
#define GEMM_THREADS 256
#define BKc 64
#define A_H_OFF 0
#define A_L_OFF 16384
#define B_H_OFF 32768
#define B_L_OFF 49152
#define STG_BYTES 65536
#define STAGES 3
#define GEMM_DSM (STAGES * STG_BYTES + 1024)

// Mainloop macro body shared by both GEMM kernels via a template-less copy.
// ---------------------------------------------------------------------------
// GEMM #1: out = x @ w_qkv + b_qkv, epilogue applies RoPE to q/k, scales q by
// (1/sqrt(dh))*log2(e), splits everything to bf16 hi/lo arrays.
// ---------------------------------------------------------------------------
__global__ __launch_bounds__(GEMM_THREADS, 1)
void gemm_qkv_rope(const __nv_bfloat16* __restrict__ Ah,
                   const __nv_bfloat16* __restrict__ Al,
                   const __nv_bfloat16* __restrict__ Bh,
                   const __nv_bfloat16* __restrict__ Bl,
                   const float* __restrict__ bias,
                   __nv_bfloat16* __restrict__ qh, __nv_bfloat16* __restrict__ ql,
                   __nv_bfloat16* __restrict__ kh, __nv_bfloat16* __restrict__ kl,
                   __nv_bfloat16* __restrict__ vh, __nv_bfloat16* __restrict__ vl)
{
    const int N = THREE_C, K = C_;
    extern __shared__ char dsm[];
    const uint32_t raw = smem_u32(dsm);
    const uint32_t sb = (raw + 1023u) & ~1023u;

    const int tid = threadIdx.x;
    const int wid = tid >> 5, lane = tid & 31;
    const int wm = (wid & 3) * 32;
    const int wn = (wid >> 2) * 64;
    const int rowBase = blockIdx.y * 128;
    const int colBase = blockIdx.x * 128;
    const int nch = K / BKc;

    auto load_stage = [&](int st, int k0) {
        uint32_t sbase = sb + st * STG_BYTES;
#pragma unroll
        for (int rep = 0; rep < 4; rep++) {
            int i = tid + rep * GEMM_THREADS;
            int row = i >> 3, cc = i & 7;
            uint32_t so = sw128((uint32_t)(row * 128 + cc * 16));
            size_t ga = (size_t)(rowBase + row) * K + k0 + cc * 8;
            size_t gb = (size_t)(colBase + row) * K + k0 + cc * 8;
            cpa16(sbase + A_H_OFF + so, Ah + ga);
            cpa16(sbase + A_L_OFF + so, Al + ga);
            cpa16(sbase + B_H_OFF + so, Bh + gb);
            cpa16(sbase + B_L_OFF + so, Bl + gb);
        }
    };

    load_stage(0, 0); CP_COMMIT();
    load_stage(1, BKc); CP_COMMIT();

    float acc[2][8][4];
#pragma unroll
    for (int mi = 0; mi < 2; mi++)
#pragma unroll
        for (int ni = 0; ni < 8; ni++)
#pragma unroll
            for (int e = 0; e < 4; e++) acc[mi][ni][e] = 0.f;

    const int lrow = lane & 15;
    const int lchunk = (lane >> 4) * 16;

    for (int c = 0; c < nch; c++) {
        CP_WAIT1();
        __syncthreads();

        int cn = c + STAGES - 1;
        if (cn < nch) load_stage(cn % STAGES, cn * BKc);
        CP_COMMIT();

        const uint32_t sbase = sb + (c % STAGES) * STG_BYTES;
        const uint32_t sAh = sbase + A_H_OFF, sAl = sbase + A_L_OFF;
        const uint32_t sBh = sbase + B_H_OFF, sBl = sbase + B_L_OFF;

#pragma unroll
        for (int ks = 0; ks < 4; ks++) {
            const int kb = ks * 32 + lchunk;
            uint32_t ah[2][4], al[2][4];
#pragma unroll
            for (int mi = 0; mi < 2; mi++) {
                uint32_t bo = sw128((uint32_t)((wm + mi * 16 + lrow) * 128 + kb));
                ldm4(ah[mi], sAh + bo);
                ldm4(al[mi], sAl + bo);
            }
            uint32_t bh[4][4], bl[4][4];
#pragma unroll
            for (int g = 0; g < 4; g++) {
                uint32_t bo = sw128((uint32_t)((wn + g * 16 + lrow) * 128 + kb));
                ldm4(bh[g], sBh + bo);
                ldm4(bl[g], sBl + bo);
            }
#pragma unroll
            for (int mi = 0; mi < 2; mi++)
#pragma unroll
                for (int ni = 0; ni < 8; ni++) {
                    int g = ni >> 1, hf = ni & 1;
                    mma16816(acc[mi][ni], ah[mi], bh[g][hf], bh[g][hf + 2]);
                    mma16816(acc[mi][ni], ah[mi], bl[g][hf], bl[g][hf + 2]);
                    mma16816(acc[mi][ni], al[mi], bh[g][hf], bh[g][hf + 2]);
                }
        }
    }

    // Epilogue: bias, RoPE on q/k pairs, q scale (1/sqrt(dh))*log2e, split hi/lo
    const float QSC = 0.08838834764831845f * 1.4426950408889634f;
    const int gro = lane >> 2, thr = lane & 3;
#pragma unroll
    for (int mi = 0; mi < 2; mi++) {
        int r0 = rowBase + wm + mi * 16 + gro;
        int t0 = r0 & (T_ - 1), t1 = (r0 + 8) & (T_ - 1);
#pragma unroll
        for (int ni = 0; ni < 8; ni++) {
            int cb = colBase + wn + ni * 8 + thr * 2;   // even
            int sel = cb >> 11;          // 0=q, 1=k, 2=v
            int jj = cb & 2047;
            float bx = bias[cb], by = bias[cb + 1];
            float v00 = acc[mi][ni][0] + bx, v01 = acc[mi][ni][1] + by;
            float v10 = acc[mi][ni][2] + bx, v11 = acc[mi][ni][3] + by;
            if (sel < 2) {
                float e = (float)jj * (1.0f / (float)C_);
                float invf = expf(-9.210340371976184f * e);
                // row r0
                float ang = (float)t0 * invf;
                float kq = rintf(ang * 0.15915494309189535f);
                float rr = fmaf(-kq, 6.28318548202514648f, ang);
                rr = fmaf(-kq, -1.7484556000744083e-7f, rr);
                float s, c;
                sincosf(rr, &s, &c);
                float o0 = v00 * c - v01 * s;
                float o1 = v00 * s + v01 * c;
                v00 = o0; v01 = o1;
                // row r0+8
                ang = (float)t1 * invf;
                kq = rintf(ang * 0.15915494309189535f);
                rr = fmaf(-kq, 6.28318548202514648f, ang);
                rr = fmaf(-kq, -1.7484556000744083e-7f, rr);
                sincosf(rr, &s, &c);
                o0 = v10 * c - v11 * s;
                o1 = v10 * s + v11 * c;
                v10 = o0; v11 = o1;
                if (sel == 0) { v00 *= QSC; v01 *= QSC; v10 *= QSC; v11 *= QSC; }
            }
            __nv_bfloat16* oh = (sel == 0) ? qh : ((sel == 1) ? kh : vh);
            __nv_bfloat16* ol = (sel == 0) ? ql : ((sel == 1) ? kl : vl);
            size_t i0 = (size_t)r0 * C_ + jj;
            size_t i1 = (size_t)(r0 + 8) * C_ + jj;
            uint32_t h0 = packbf(v00, v01);
            __nv_bfloat162 hv0 = *(__nv_bfloat162*)&h0;
            uint32_t l0 = packbf(v00 - __bfloat162float(hv0.x),
                                 v01 - __bfloat162float(hv0.y));
            uint32_t h1 = packbf(v10, v11);
            __nv_bfloat162 hv1 = *(__nv_bfloat162*)&h1;
            uint32_t l1 = packbf(v10 - __bfloat162float(hv1.x),
                                 v11 - __bfloat162float(hv1.y));
            *(uint32_t*)(oh + i0) = h0;
            *(uint32_t*)(ol + i0) = l0;
            *(uint32_t*)(oh + i1) = h1;
            *(uint32_t*)(ol + i1) = l1;
        }
    }
}

// ---------------------------------------------------------------------------
// GEMM #2: out = y @ w_proj + b_proj (fp32 out) — unchanged R9/R10 kernel.
// ---------------------------------------------------------------------------
__global__ __launch_bounds__(GEMM_THREADS, 1)
void gemm_hmma_bf16x3(const __nv_bfloat16* __restrict__ Ah,
                      const __nv_bfloat16* __restrict__ Al,
                      const __nv_bfloat16* __restrict__ Bh,
                      const __nv_bfloat16* __restrict__ Bl,
                      const float* __restrict__ bias, float* __restrict__ Cm,
                      int N, int K)
{
    extern __shared__ char dsm[];
    const uint32_t raw = smem_u32(dsm);
    const uint32_t sb = (raw + 1023u) & ~1023u;

    const int tid = threadIdx.x;
    const int wid = tid >> 5, lane = tid & 31;
    const int wm = (wid & 3) * 32;
    const int wn = (wid >> 2) * 64;
    const int rowBase = blockIdx.y * 128;
    const int colBase = blockIdx.x * 128;
    const int nch = K / BKc;

    auto load_stage = [&](int st, int k0) {
        uint32_t sbase = sb + st * STG_BYTES;
#pragma unroll
        for (int rep = 0; rep < 4; rep++) {
            int i = tid + rep * GEMM_THREADS;
            int row = i >> 3, cc = i & 7;
            uint32_t so = sw128((uint32_t)(row * 128 + cc * 16));
            size_t ga = (size_t)(rowBase + row) * K + k0 + cc * 8;
            size_t gb = (size_t)(colBase + row) * K + k0 + cc * 8;
            cpa16(sbase + A_H_OFF + so, Ah + ga);
            cpa16(sbase + A_L_OFF + so, Al + ga);
            cpa16(sbase + B_H_OFF + so, Bh + gb);
            cpa16(sbase + B_L_OFF + so, Bl + gb);
        }
    };

    load_stage(0, 0); CP_COMMIT();
    load_stage(1, BKc); CP_COMMIT();

    float acc[2][8][4];
#pragma unroll
    for (int mi = 0; mi < 2; mi++)
#pragma unroll
        for (int ni = 0; ni < 8; ni++)
#pragma unroll
            for (int e = 0; e < 4; e++) acc[mi][ni][e] = 0.f;

    const int lrow = lane & 15;
    const int lchunk = (lane >> 4) * 16;

    for (int c = 0; c < nch; c++) {
        CP_WAIT1();
        __syncthreads();

        int cn = c + STAGES - 1;
        if (cn < nch) load_stage(cn % STAGES, cn * BKc);
        CP_COMMIT();

        const uint32_t sbase = sb + (c % STAGES) * STG_BYTES;
        const uint32_t sAh = sbase + A_H_OFF, sAl = sbase + A_L_OFF;
        const uint32_t sBh = sbase + B_H_OFF, sBl = sbase + B_L_OFF;

#pragma unroll
        for (int ks = 0; ks < 4; ks++) {
            const int kb = ks * 32 + lchunk;
            uint32_t ah[2][4], al[2][4];
#pragma unroll
            for (int mi = 0; mi < 2; mi++) {
                uint32_t bo = sw128((uint32_t)((wm + mi * 16 + lrow) * 128 + kb));
                ldm4(ah[mi], sAh + bo);
                ldm4(al[mi], sAl + bo);
            }
            uint32_t bh[4][4], bl[4][4];
#pragma unroll
            for (int g = 0; g < 4; g++) {
                uint32_t bo = sw128((uint32_t)((wn + g * 16 + lrow) * 128 + kb));
                ldm4(bh[g], sBh + bo);
                ldm4(bl[g], sBl + bo);
            }
#pragma unroll
            for (int mi = 0; mi < 2; mi++)
#pragma unroll
                for (int ni = 0; ni < 8; ni++) {
                    int g = ni >> 1, hf = ni & 1;
                    mma16816(acc[mi][ni], ah[mi], bh[g][hf], bh[g][hf + 2]);
                    mma16816(acc[mi][ni], ah[mi], bl[g][hf], bl[g][hf + 2]);
                    mma16816(acc[mi][ni], al[mi], bh[g][hf], bh[g][hf + 2]);
                }
        }
    }

    const int gro = lane >> 2, thr = lane & 3;
#pragma unroll
    for (int mi = 0; mi < 2; mi++) {
        int r0 = rowBase + wm + mi * 16 + gro;
#pragma unroll
        for (int ni = 0; ni < 8; ni++) {
            int cb = colBase + wn + ni * 8 + thr * 2;
            float bx = bias[cb], by = bias[cb + 1];
            float2 o0, o1;
            o0.x = acc[mi][ni][0] + bx; o0.y = acc[mi][ni][1] + by;
            o1.x = acc[mi][ni][2] + bx; o1.y = acc[mi][ni][3] + by;
            *(float2*)(Cm + (size_t)r0 * N + cb) = o0;
            *(float2*)(Cm + (size_t)(r0 + 8) * N + cb) = o1;
        }
    }
}

// ---------------------------------------------------------------------------
// HMMA flash attention v2: bf16 hi/lo inputs precomputed (roped, scaled),
// cp.async double-buffered KV, ex2-based softmax (base-2), bf16 hi/lo output.
// CTA = (128-row q tile, h, b), 256 threads, 8 warps x 16 q rows.
// SMEM: Q hi/lo 64KB @ 0; 2 KV stages of 64KB @ 65536 (KH,KL,VH,VL 16KB each).
// ---------------------------------------------------------------------------
#define AQH 0
#define AQL 32768
#define KVST 65536
#define KH_O 0
#define KL_O 16384
#define VH_O 32768
#define VL_O 49152
#define ATTN2_DSM (65536 + 2 * 65536 + 1024)

__global__ __launch_bounds__(256, 1)
void attn_hmma2(const __nv_bfloat16* __restrict__ qh, const __nv_bfloat16* __restrict__ ql,
                const __nv_bfloat16* __restrict__ kh, const __nv_bfloat16* __restrict__ kl,
                const __nv_bfloat16* __restrict__ vh, const __nv_bfloat16* __restrict__ vl,
                __nv_bfloat16* __restrict__ yh, __nv_bfloat16* __restrict__ yl)
{
    extern __shared__ char asmem[];
    const uint32_t raw = smem_u32(asmem);
    const uint32_t sb = (raw + 1023u) & ~1023u;

    const int qt = blockIdx.x, h = blockIdx.y, b = blockIdx.z;
    const int qb = qt * 128;
    const int tid = threadIdx.x;
    const int wid = tid >> 5, lane = tid & 31;
    const int wq0 = wid * 16;
    const int lrow = lane & 15;
    const int lch = (lane >> 4) * 16;
    const int gro = lane >> 2, thr = lane & 3;
    const uint32_t rx = ((uint32_t)(lrow & 7)) << 4;

    // ---- Q tile via cp.async (already roped + scaled by SCALE*log2e) ----
#pragma unroll
    for (int rep = 0; rep < 8; rep++) {
        int idx = tid + rep * 256;
        int row = idx >> 4, ch = idx & 15;
        uint32_t so = (uint32_t)row * 256 +
                      (((uint32_t)(ch * 16)) ^ (((uint32_t)(row & 7)) << 4));
        size_t g = ((size_t)(b * T_ + qb + row)) * C_ + h * DH + ch * 8;
        cpa16(sb + AQH + so, qh + g);
        cpa16(sb + AQL + so, ql + g);
    }

    auto loadKV = [&](int st, int j2) {
        uint32_t stb = sb + KVST + st * 65536;
        size_t grow = ((size_t)(b * T_ + j2 * 64)) * C_ + h * DH;
#pragma unroll
        for (int rep = 0; rep < 4; rep++) {
            int idx = tid + rep * 256;
            int row = idx >> 4, ch = idx & 15;
            uint32_t so = (uint32_t)row * 256 +
                          (((uint32_t)(ch * 16)) ^ (((uint32_t)(row & 7)) << 4));
            size_t g = grow + (size_t)row * C_ + ch * 8;
            cpa16(stb + KH_O + so, kh + g);
            cpa16(stb + KL_O + so, kl + g);
            cpa16(stb + VH_O + so, vh + g);
            cpa16(stb + VL_O + so, vl + g);
        }
    };

    loadKV(0, 0);
    CP_COMMIT();

    float m0 = -INFINITY, m1 = -INFINITY, l0 = 0.f, l1 = 0.f;
    float O[16][4];
#pragma unroll
    for (int i = 0; i < 16; i++)
#pragma unroll
        for (int e = 0; e < 4; e++) O[i][e] = 0.f;

    const int ntiles = 2 * qt + 2;
    for (int j = 0; j < ntiles; j++) {
        const int kvg = j * 64;
        CP_WAIT0();
        __syncthreads();   // tile j visible; all warps done with buffer (j&1)

        if (j + 1 < ntiles) { loadKV((j + 1) & 1, j + 1); CP_COMMIT(); }

        const uint32_t stb = sb + KVST + (j & 1) * 65536;
        const uint32_t sKH = stb + KH_O, sKL = stb + KL_O;
        const uint32_t sVH = stb + VH_O, sVL = stb + VL_O;

        // ---- S = Q K^T (3-term bf16x3), S in log2 domain ----
        float c[8][4];
#pragma unroll
        for (int nt = 0; nt < 8; nt++)
#pragma unroll
            for (int e = 0; e < 4; e++) c[nt][e] = 0.f;

#pragma unroll
        for (int kc = 0; kc < 8; kc++) {
            const uint32_t kb = (uint32_t)(kc * 32 + lch);
            uint32_t aqh[4], aql[4];
            {
                uint32_t off = (uint32_t)(wq0 + lrow) * 256 + (kb ^ rx);
                ldm4(aqh, sb + AQH + off);
                ldm4(aql, sb + AQL + off);
            }
#pragma unroll
            for (int g4 = 0; g4 < 4; g4++) {
                uint32_t off = (uint32_t)(g4 * 16 + lrow) * 256 + (kb ^ rx);
                uint32_t bh[4], bl[4];
                ldm4(bh, sKH + off);
                ldm4(bl, sKL + off);
#pragma unroll
                for (int hf = 0; hf < 2; hf++) {
                    int nt = g4 * 2 + hf;
                    mma16816(c[nt], aqh, bh[hf], bh[hf + 2]);
                    mma16816(c[nt], aqh, bl[hf], bl[hf + 2]);
                    mma16816(c[nt], aql, bh[hf], bh[hf + 2]);
                }
            }
        }

        // ---- Causal mask ----
        const int row_lo = qb + wq0 + gro;
        const int row_hi = row_lo + 8;
        if (kvg + 63 > qb + wq0) {
#pragma unroll
            for (int nt = 0; nt < 8; nt++) {
                int cbase = kvg + nt * 8 + 2 * thr;
                if (cbase > row_lo)     c[nt][0] = -1e30f;
                if (cbase + 1 > row_lo) c[nt][1] = -1e30f;
                if (cbase > row_hi)     c[nt][2] = -1e30f;
                if (cbase + 1 > row_hi) c[nt][3] = -1e30f;
            }
        }

        // ---- Online softmax (base-2, rows gro and gro+8) ----
        float mt0 = -1e30f, mt1 = -1e30f;
#pragma unroll
        for (int nt = 0; nt < 8; nt++) {
            mt0 = fmaxf(mt0, fmaxf(c[nt][0], c[nt][1]));
            mt1 = fmaxf(mt1, fmaxf(c[nt][2], c[nt][3]));
        }
        mt0 = fmaxf(mt0, __shfl_xor_sync(0xffffffffu, mt0, 1));
        mt0 = fmaxf(mt0, __shfl_xor_sync(0xffffffffu, mt0, 2));
        mt1 = fmaxf(mt1, __shfl_xor_sync(0xffffffffu, mt1, 1));
        mt1 = fmaxf(mt1, __shfl_xor_sync(0xffffffffu, mt1, 2));
        float mn0 = fmaxf(m0, mt0), mn1 = fmaxf(m1, mt1);
        float cor0 = ex2f(m0 - mn0), cor1 = ex2f(m1 - mn1);
        float s0 = 0.f, s1 = 0.f;
#pragma unroll
        for (int nt = 0; nt < 8; nt++) {
            c[nt][0] = ex2f(c[nt][0] - mn0); s0 += c[nt][0];
            c[nt][1] = ex2f(c[nt][1] - mn0); s0 += c[nt][1];
            c[nt][2] = ex2f(c[nt][2] - mn1); s1 += c[nt][2];
            c[nt][3] = ex2f(c[nt][3] - mn1); s1 += c[nt][3];
        }
        s0 += __shfl_xor_sync(0xffffffffu, s0, 1);
        s0 += __shfl_xor_sync(0xffffffffu, s0, 2);
        s1 += __shfl_xor_sync(0xffffffffu, s1, 1);
        s1 += __shfl_xor_sync(0xffffffffu, s1, 2);
        l0 = l0 * cor0 + s0; m0 = mn0;
        l1 = l1 * cor1 + s1; m1 = mn1;
#pragma unroll
        for (int i = 0; i < 16; i++) {
            O[i][0] *= cor0; O[i][1] *= cor0;
            O[i][2] *= cor1; O[i][3] *= cor1;
        }

        // ---- O += P V (3-term; P hi/lo built in registers) ----
        const uint32_t rxv = ((uint32_t)(lane & 7)) << 4;
        const uint32_t colb = (uint32_t)((lane >> 3) & 1) * 16;
#pragma unroll
        for (int kc2 = 0; kc2 < 4; kc2++) {
            uint32_t aph[4], apl[4];
            {
                float p00 = c[2 * kc2][0], p01 = c[2 * kc2][1];
                float p10 = c[2 * kc2][2], p11 = c[2 * kc2][3];
                float p20 = c[2 * kc2 + 1][0], p21 = c[2 * kc2 + 1][1];
                float p30 = c[2 * kc2 + 1][2], p31 = c[2 * kc2 + 1][3];
                aph[0] = packbf(p00, p01);
                aph[1] = packbf(p10, p11);
                aph[2] = packbf(p20, p21);
                aph[3] = packbf(p30, p31);
                __nv_bfloat162* t;
                t = (__nv_bfloat162*)&aph[0];
                apl[0] = packbf(p00 - __bfloat162float(t->x), p01 - __bfloat162float(t->y));
                t = (__nv_bfloat162*)&aph[1];
                apl[1] = packbf(p10 - __bfloat162float(t->x), p11 - __bfloat162float(t->y));
                t = (__nv_bfloat162*)&aph[2];
                apl[2] = packbf(p20 - __bfloat162float(t->x), p21 - __bfloat162float(t->y));
                t = (__nv_bfloat162*)&aph[3];
                apl[3] = packbf(p30 - __bfloat162float(t->x), p31 - __bfloat162float(t->y));
            }
            const uint32_t vrow = (uint32_t)(kc2 * 16 + (lane & 7) + (lane >> 4) * 8);
#pragma unroll
            for (int gg = 0; gg < 8; gg++) {
                uint32_t off = vrow * 256 + (((uint32_t)(gg * 32) + colb) ^ rxv);
                uint32_t vhf[4], vlf[4];
                ldm4t(vhf, sVH + off);
                ldm4t(vlf, sVL + off);
#pragma unroll
                for (int hf = 0; hf < 2; hf++) {
                    int nt2 = gg * 2 + hf;
                    mma16816(O[nt2], aph, vhf[hf], vhf[hf + 2]);
                    mma16816(O[nt2], aph, vlf[hf], vlf[hf + 2]);
                    mma16816(O[nt2], apl, vhf[hf], vhf[hf + 2]);
                }
            }
        }
    }

    // ---- Epilogue: normalize, split hi/lo, store y bf16 arrays ----
    const float il0 = 1.f / l0, il1 = 1.f / l1;
    const int row_lo = qb + wq0 + gro;
    size_t r0o = (size_t)(b * T_ + row_lo) * C_;
    size_t r1o = (size_t)(b * T_ + row_lo + 8) * C_;
#pragma unroll
    for (int nt2 = 0; nt2 < 16; nt2++) {
        int col = h * DH + nt2 * 8 + 2 * thr;
        float a0 = O[nt2][0] * il0, a1 = O[nt2][1] * il0;
        float b0 = O[nt2][2] * il1, b1 = O[nt2][3] * il1;
        uint32_t h0 = packbf(a0, a1);
        __nv_bfloat162 hv0 = *(__nv_bfloat162*)&h0;
        uint32_t l0w = packbf(a0 - __bfloat162float(hv0.x), a1 - __bfloat162float(hv0.y));
        uint32_t h1 = packbf(b0, b1);
        __nv_bfloat162 hv1 = *(__nv_bfloat162*)&h1;
        uint32_t l1w = packbf(b0 - __bfloat162float(hv1.x), b1 - __bfloat162float(hv1.y));
        *(uint32_t*)(yh + r0o + col) = h0;
        *(uint32_t*)(yl + r0o + col) = l0w;
        *(uint32_t*)(yh + r1o + col) = h1;
        *(uint32_t*)(yl + r1o + col) = l1w;
    }
}

// ---------------------------------------------------------------------------
// Launch
// ---------------------------------------------------------------------------
extern "C" void kernel_launch(void* const* d_in, const int* in_sizes, int n_in,
                              void* d_out, int out_size)
{
    (void)in_sizes; (void)n_in; (void)out_size;
    const float* x      = (const float*)d_in[0];
    const float* w_qkv  = (const float*)d_in[1];
    const float* b_qkv  = (const float*)d_in[2];
    const float* w_proj = (const float*)d_in[3];
    const float* b_proj = (const float*)d_in[4];
    float* out = (float*)d_out;

    void *p_xh, *p_xl, *p_yh, *p_yl, *p_wqh, *p_wql, *p_wph, *p_wpl;
    void *p_qh, *p_ql, *p_kh, *p_kl, *p_vh, *p_vl;
    cudaGetSymbolAddress(&p_xh, g_xc_h);
    cudaGetSymbolAddress(&p_xl, g_xc_l);
    cudaGetSymbolAddress(&p_yh, g_yc_h);
    cudaGetSymbolAddress(&p_yl, g_yc_l);
    cudaGetSymbolAddress(&p_wqh, g_wq_h);
    cudaGetSymbolAddress(&p_wql, g_wq_l);
    cudaGetSymbolAddress(&p_wph, g_wp_h);
    cudaGetSymbolAddress(&p_wpl, g_wp_l);
    cudaGetSymbolAddress(&p_qh, g_qh);
    cudaGetSymbolAddress(&p_ql, g_ql);
    cudaGetSymbolAddress(&p_kh, g_kh);
    cudaGetSymbolAddress(&p_kl, g_kl);
    cudaGetSymbolAddress(&p_vh, g_vh);
    cudaGetSymbolAddress(&p_vl, g_vl);

    cudaFuncSetAttribute(gemm_qkv_rope,
                         cudaFuncAttributeMaxDynamicSharedMemorySize, GEMM_DSM);
    cudaFuncSetAttribute(gemm_hmma_bf16x3,
                         cudaFuncAttributeMaxDynamicSharedMemorySize, GEMM_DSM);
    cudaFuncSetAttribute(attn_hmma2,
                         cudaFuncAttributeMaxDynamicSharedMemorySize, ATTN2_DSM);

    // 0) Weight transpose+split and x split
    wconv<<<dim3(THREE_C / 32, C_ / 32), dim3(32, 8)>>>(
        w_qkv, (__nv_bfloat16*)p_wqh, (__nv_bfloat16*)p_wql, C_, THREE_C);
    wconv<<<dim3(C_ / 32, C_ / 32), dim3(32, 8)>>>(
        w_proj, (__nv_bfloat16*)p_wph, (__nv_bfloat16*)p_wpl, C_, C_);
    {
        long n8 = (long)M_ * C_ / 8;
        convert_hilo<<<(int)((n8 + 255) / 256), 256>>>(
            x, (__nv_bfloat16*)p_xh, (__nv_bfloat16*)p_xl, n8);
    }

    // 1) QKV GEMM + fused bias + RoPE + scale + bf16 hi/lo split
    gemm_qkv_rope<<<dim3(THREE_C / 128, M_ / 128), GEMM_THREADS, GEMM_DSM>>>(
        (const __nv_bfloat16*)p_xh, (const __nv_bfloat16*)p_xl,
        (const __nv_bfloat16*)p_wqh, (const __nv_bfloat16*)p_wql,
        b_qkv,
        (__nv_bfloat16*)p_qh, (__nv_bfloat16*)p_ql,
        (__nv_bfloat16*)p_kh, (__nv_bfloat16*)p_kl,
        (__nv_bfloat16*)p_vh, (__nv_bfloat16*)p_vl);

    // 2) Causal flash attention (HMMA bf16x3, cp.async, ex2) -> y hi/lo
    {
        dim3 grid(T_ / 128, H_, B_);
        attn_hmma2<<<grid, 256, ATTN2_DSM>>>(
            (const __nv_bfloat16*)p_qh, (const __nv_bfloat16*)p_ql,
            (const __nv_bfloat16*)p_kh, (const __nv_bfloat16*)p_kl,
            (const __nv_bfloat16*)p_vh, (const __nv_bfloat16*)p_vl,
            (__nv_bfloat16*)p_yh, (__nv_bfloat16*)p_yl);
    }

    // 3) out = y @ w_proj + b_proj (HMMA bf16x3, fp32 out)
    gemm_hmma_bf16x3<<<dim3(C_ / 128, M_ / 128), GEMM_THREADS, GEMM_DSM>>>(
        (const __nv_bfloat16*)p_yh, (const __nv_bfloat16*)p_yl,
        (const __nv_bfloat16*)p_wph, (const __nv_bfloat16*)p_wpl,
        b_proj, out, C_, C_);
}

// round 12
// speedup vs baseline: 2.6164x; 1.0095x over previous
#include <cuda_runtime.h>
#include <cuda_bf16.h>
#include <math.h>
#include <stdint.h>

// Problem constants
#define B_ 4
#define T_ 2048
#define C_ 2048
#define H_ 16
#define DH 128
#define THREE_C (3 * C_)
#define M_ (B_ * T_)   // 8192

// ---------------------------------------------------------------------------
// Device-global scratch (allocation-free)
// ---------------------------------------------------------------------------
__device__ __nv_bfloat16 g_xc_h[(size_t)M_ * C_];
__device__ __nv_bfloat16 g_xc_l[(size_t)M_ * C_];
__device__ __nv_bfloat16 g_yc_h[(size_t)M_ * C_];
__device__ __nv_bfloat16 g_yc_l[(size_t)M_ * C_];
__device__ __nv_bfloat16 g_wq_h[(size_t)THREE_C * C_];      // w_qkv^T [6144,2048]
__device__ __nv_bfloat16 g_wq_l[(size_t)THREE_C * C_];
__device__ __nv_bfloat16 g_wp_h[(size_t)C_ * C_];           // w_proj^T [2048,2048]
__device__ __nv_bfloat16 g_wp_l[(size_t)C_ * C_];
// Roped/scaled bf16 hi/lo Q,K and split V, layout [M_][C_] (c = h*128+d)
__device__ __nv_bfloat16 g_qh[(size_t)M_ * C_];
__device__ __nv_bfloat16 g_ql[(size_t)M_ * C_];
__device__ __nv_bfloat16 g_kh[(size_t)M_ * C_];
__device__ __nv_bfloat16 g_kl[(size_t)M_ * C_];
__device__ __nv_bfloat16 g_vh[(size_t)M_ * C_];
__device__ __nv_bfloat16 g_vl[(size_t)M_ * C_];

// ---------------------------------------------------------------------------
// Helpers
// ---------------------------------------------------------------------------
__device__ __forceinline__ uint32_t smem_u32(const void* p) {
    uint32_t a;
    asm("{ .reg .u64 t; cvta.to.shared.u64 t, %1; cvt.u32.u64 %0, t; }"
        : "=r"(a) : "l"(p));
    return a;
}
static __device__ __forceinline__ uint32_t sw128(uint32_t x) {
    return x ^ ((x >> 3) & 0x70);
}
__device__ __forceinline__ void cpa16(uint32_t s, const void* g) {
    asm volatile("cp.async.cg.shared.global [%0], [%1], 16;" :: "r"(s), "l"(g));
}
#define CP_COMMIT() asm volatile("cp.async.commit_group;" ::: "memory")
#define CP_WAIT1()  asm volatile("cp.async.wait_group 1;" ::: "memory")
#define CP_WAIT0()  asm volatile("cp.async.wait_group 0;" ::: "memory")

__device__ __forceinline__ void ldm4(uint32_t* r, uint32_t addr) {
    asm volatile("ldmatrix.sync.aligned.m8n8.x4.shared.b16 {%0,%1,%2,%3}, [%4];"
                 : "=r"(r[0]), "=r"(r[1]), "=r"(r[2]), "=r"(r[3]) : "r"(addr));
}
__device__ __forceinline__ void ldm4t(uint32_t* r, uint32_t addr) {
    asm volatile("ldmatrix.sync.aligned.m8n8.x4.trans.shared.b16 {%0,%1,%2,%3}, [%4];"
                 : "=r"(r[0]), "=r"(r[1]), "=r"(r[2]), "=r"(r[3]) : "r"(addr));
}
__device__ __forceinline__ void mma16816(float* d, const uint32_t* a,
                                         uint32_t b0, uint32_t b1) {
    asm volatile(
        "mma.sync.aligned.m16n8k16.row.col.f32.bf16.bf16.f32 "
        "{%0,%1,%2,%3}, {%4,%5,%6,%7}, {%8,%9}, {%0,%1,%2,%3};"
        : "+f"(d[0]), "+f"(d[1]), "+f"(d[2]), "+f"(d[3])
        : "r"(a[0]), "r"(a[1]), "r"(a[2]), "r"(a[3]), "r"(b0), "r"(b1));
}
__device__ __forceinline__ uint32_t packbf(float a, float b) {
    __nv_bfloat162 t = __floats2bfloat162_rn(a, b);   // .x = a (low 16 bits)
    return *(uint32_t*)&t;
}
__device__ __forceinline__ float ex2f(float x) {
    float r;
    asm("ex2.approx.f32 %0, %1;" : "=f"(r) : "f"(x));
    return r;
}

// ---------------------------------------------------------------------------
// Elementwise fp32 -> bf16 (hi, lo) split. n8 = elements/8.
// ---------------------------------------------------------------------------
__global__ void convert_hilo(const float* __restrict__ X,
                             __nv_bfloat16* __restrict__ Hh,
                             __nv_bfloat16* __restrict__ Hl, long n8)
{
    long i = (long)blockIdx.x * blockDim.x + threadIdx.x;
    if (i >= n8) return;
    float4 a = ((const float4*)X)[i * 2 + 0];
    float4 b = ((const float4*)X)[i * 2 + 1];
    float v[8] = {a.x, a.y, a.z, a.w, b.x, b.y, b.z, b.w};
    union { __nv_bfloat16 e[8]; uint4 u; } ph, pl;
#pragma unroll
    for (int j = 0; j < 8; j++) {
        __nv_bfloat16 h = __float2bfloat16(v[j]);
        ph.e[j] = h;
        pl.e[j] = __float2bfloat16(v[j] - __bfloat162float(h));
    }
    ((uint4*)Hh)[i] = ph.u;
    ((uint4*)Hl)[i] = pl.u;
}

// ---------------------------------------------------------------------------
// Transpose + split: W[K,N] fp32 row-major -> Th/Tl [N,K] bf16 row-major
// ---------------------------------------------------------------------------
__global__ void wconv(const float* __restrict__ W, __nv_bfloat16* __restrict__ Th,
                      __nv_bfloat16* __restrict__ Tl, int K, int N)
{
    __shared__ float ts[32][33];
    int n0 = blockIdx.x * 32, k0 = blockIdx.y * 32;
    int tx = threadIdx.x, ty = threadIdx.y;
    for (int i = ty; i < 32; i += 8)
        ts[i][tx] = W[(size_t)(k0 + i) * N + n0 + tx];
    __syncthreads();
    for (int i = ty; i < 32; i += 8) {
        float v = ts[tx][i];
        __nv_bfloat16 h = __float2bfloat16(v);
        __nv_bfloat16 l = __float2bfloat16(v - __bfloat162float(h));
        size_t o = (size_t)(n0 + i) * K + k0 + tx;
        Th[o] = h;
        Tl[o] = l;
    }
}

// ---------------------------------------------------------------------------
// Shared GEMM config (CTA 128x128, BK=64, 3-stage cp.async, 256 thr)
// ---------------------------------------------------------------------------
#define GEMM_THREADS 256
#define BKc 64
#define A_H_OFF 0
#define A_L_OFF 16384
#define B_H_OFF 32768
#define B_L_OFF 49152
#define STG_BYTES 65536
#define STAGES 3
#define GEMM_DSM (STAGES * STG_BYTES + 1024)

// ---------------------------------------------------------------------------
// GEMM #1: out = x @ w_qkv + b_qkv, epilogue applies RoPE to q/k, scales q by
// (1/sqrt(dh))*log2(e), splits everything to bf16 hi/lo arrays.
// ---------------------------------------------------------------------------
__global__ __launch_bounds__(GEMM_THREADS, 1)
void gemm_qkv_rope(const __nv_bfloat16* __restrict__ Ah,
                   const __nv_bfloat16* __restrict__ Al,
                   const __nv_bfloat16* __restrict__ Bh,
                   const __nv_bfloat16* __restrict__ Bl,
                   const float* __restrict__ bias,
                   __nv_bfloat16* __restrict__ qh, __nv_bfloat16* __restrict__ ql,
                   __nv_bfloat16* __restrict__ kh, __nv_bfloat16* __restrict__ kl,
                   __nv_bfloat16* __restrict__ vh, __nv_bfloat16* __restrict__ vl)
{
    const int K = C_;
    extern __shared__ char dsm[];
    const uint32_t raw = smem_u32(dsm);
    const uint32_t sb = (raw + 1023u) & ~1023u;

    const int tid = threadIdx.x;
    const int wid = tid >> 5, lane = tid & 31;
    const int wm = (wid & 3) * 32;
    const int wn = (wid >> 2) * 64;
    const int rowBase = blockIdx.y * 128;
    const int colBase = blockIdx.x * 128;
    const int nch = K / BKc;

    auto load_stage = [&](int st, int k0) {
        uint32_t sbase = sb + st * STG_BYTES;
#pragma unroll
        for (int rep = 0; rep < 4; rep++) {
            int i = tid + rep * GEMM_THREADS;
            int row = i >> 3, cc = i & 7;
            uint32_t so = sw128((uint32_t)(row * 128 + cc * 16));
            size_t ga = (size_t)(rowBase + row) * K + k0 + cc * 8;
            size_t gb = (size_t)(colBase + row) * K + k0 + cc * 8;
            cpa16(sbase + A_H_OFF + so, Ah + ga);
            cpa16(sbase + A_L_OFF + so, Al + ga);
            cpa16(sbase + B_H_OFF + so, Bh + gb);
            cpa16(sbase + B_L_OFF + so, Bl + gb);
        }
    };

    load_stage(0, 0); CP_COMMIT();
    load_stage(1, BKc); CP_COMMIT();

    float acc[2][8][4];
#pragma unroll
    for (int mi = 0; mi < 2; mi++)
#pragma unroll
        for (int ni = 0; ni < 8; ni++)
#pragma unroll
            for (int e = 0; e < 4; e++) acc[mi][ni][e] = 0.f;

    const int lrow = lane & 15;
    const int lchunk = (lane >> 4) * 16;

    for (int c = 0; c < nch; c++) {
        CP_WAIT1();
        __syncthreads();

        int cn = c + STAGES - 1;
        if (cn < nch) load_stage(cn % STAGES, cn * BKc);
        CP_COMMIT();

        const uint32_t sbase = sb + (c % STAGES) * STG_BYTES;
        const uint32_t sAh = sbase + A_H_OFF, sAl = sbase + A_L_OFF;
        const uint32_t sBh = sbase + B_H_OFF, sBl = sbase + B_L_OFF;

#pragma unroll
        for (int ks = 0; ks < 4; ks++) {
            const int kb = ks * 32 + lchunk;
            uint32_t ah[2][4], al[2][4];
#pragma unroll
            for (int mi = 0; mi < 2; mi++) {
                uint32_t bo = sw128((uint32_t)((wm + mi * 16 + lrow) * 128 + kb));
                ldm4(ah[mi], sAh + bo);
                ldm4(al[mi], sAl + bo);
            }
            uint32_t bh[4][4], bl[4][4];
#pragma unroll
            for (int g = 0; g < 4; g++) {
                uint32_t bo = sw128((uint32_t)((wn + g * 16 + lrow) * 128 + kb));
                ldm4(bh[g], sBh + bo);
                ldm4(bl[g], sBl + bo);
            }
#pragma unroll
            for (int mi = 0; mi < 2; mi++)
#pragma unroll
                for (int ni = 0; ni < 8; ni++) {
                    int g = ni >> 1, hf = ni & 1;
                    mma16816(acc[mi][ni], ah[mi], bh[g][hf], bh[g][hf + 2]);
                    mma16816(acc[mi][ni], ah[mi], bl[g][hf], bl[g][hf + 2]);
                    mma16816(acc[mi][ni], al[mi], bh[g][hf], bh[g][hf + 2]);
                }
        }
    }

    // Epilogue: bias, RoPE on q/k pairs, q scale (1/sqrt(dh))*log2e, split hi/lo
    const float QSC = 0.08838834764831845f * 1.4426950408889634f;
    const int gro = lane >> 2, thr = lane & 3;
#pragma unroll
    for (int mi = 0; mi < 2; mi++) {
        int r0 = rowBase + wm + mi * 16 + gro;
        int t0 = r0 & (T_ - 1), t1 = (r0 + 8) & (T_ - 1);
#pragma unroll
        for (int ni = 0; ni < 8; ni++) {
            int cb = colBase + wn + ni * 8 + thr * 2;   // even
            int sel = cb >> 11;          // 0=q, 1=k, 2=v
            int jj = cb & 2047;
            float bx = bias[cb], by = bias[cb + 1];
            float v00 = acc[mi][ni][0] + bx, v01 = acc[mi][ni][1] + by;
            float v10 = acc[mi][ni][2] + bx, v11 = acc[mi][ni][3] + by;
            if (sel < 2) {
                float e = (float)jj * (1.0f / (float)C_);
                float invf = expf(-9.210340371976184f * e);
                float ang = (float)t0 * invf;
                float kq = rintf(ang * 0.15915494309189535f);
                float rr = fmaf(-kq, 6.28318548202514648f, ang);
                rr = fmaf(-kq, -1.7484556000744083e-7f, rr);
                float s, c;
                sincosf(rr, &s, &c);
                float o0 = v00 * c - v01 * s;
                float o1 = v00 * s + v01 * c;
                v00 = o0; v01 = o1;
                ang = (float)t1 * invf;
                kq = rintf(ang * 0.15915494309189535f);
                rr = fmaf(-kq, 6.28318548202514648f, ang);
                rr = fmaf(-kq, -1.7484556000744083e-7f, rr);
                sincosf(rr, &s, &c);
                o0 = v10 * c - v11 * s;
                o1 = v10 * s + v11 * c;
                v10 = o0; v11 = o1;
                if (sel == 0) { v00 *= QSC; v01 *= QSC; v10 *= QSC; v11 *= QSC; }
            }
            __nv_bfloat16* oh = (sel == 0) ? qh : ((sel == 1) ? kh : vh);
            __nv_bfloat16* ol = (sel == 0) ? ql : ((sel == 1) ? kl : vl);
            size_t i0 = (size_t)r0 * C_ + jj;
            size_t i1 = (size_t)(r0 + 8) * C_ + jj;
            uint32_t h0 = packbf(v00, v01);
            __nv_bfloat162 hv0 = *(__nv_bfloat162*)&h0;
            uint32_t l0 = packbf(v00 - __bfloat162float(hv0.x),
                                 v01 - __bfloat162float(hv0.y));
            uint32_t h1 = packbf(v10, v11);
            __nv_bfloat162 hv1 = *(__nv_bfloat162*)&h1;
            uint32_t l1 = packbf(v10 - __bfloat162float(hv1.x),
                                 v11 - __bfloat162float(hv1.y));
            *(uint32_t*)(oh + i0) = h0;
            *(uint32_t*)(ol + i0) = l0;
            *(uint32_t*)(oh + i1) = h1;
            *(uint32_t*)(ol + i1) = l1;
        }
    }
}

// ---------------------------------------------------------------------------
// GEMM #2: out = y @ w_proj + b_proj (fp32 out)
// ---------------------------------------------------------------------------
__global__ __launch_bounds__(GEMM_THREADS, 1)
void gemm_hmma_bf16x3(const __nv_bfloat16* __restrict__ Ah,
                      const __nv_bfloat16* __restrict__ Al,
                      const __nv_bfloat16* __restrict__ Bh,
                      const __nv_bfloat16* __restrict__ Bl,
                      const float* __restrict__ bias, float* __restrict__ Cm,
                      int N, int K)
{
    extern __shared__ char dsm[];
    const uint32_t raw = smem_u32(dsm);
    const uint32_t sb = (raw + 1023u) & ~1023u;

    const int tid = threadIdx.x;
    const int wid = tid >> 5, lane = tid & 31;
    const int wm = (wid & 3) * 32;
    const int wn = (wid >> 2) * 64;
    const int rowBase = blockIdx.y * 128;
    const int colBase = blockIdx.x * 128;
    const int nch = K / BKc;

    auto load_stage = [&](int st, int k0) {
        uint32_t sbase = sb + st * STG_BYTES;
#pragma unroll
        for (int rep = 0; rep < 4; rep++) {
            int i = tid + rep * GEMM_THREADS;
            int row = i >> 3, cc = i & 7;
            uint32_t so = sw128((uint32_t)(row * 128 + cc * 16));
            size_t ga = (size_t)(rowBase + row) * K + k0 + cc * 8;
            size_t gb = (size_t)(colBase + row) * K + k0 + cc * 8;
            cpa16(sbase + A_H_OFF + so, Ah + ga);
            cpa16(sbase + A_L_OFF + so, Al + ga);
            cpa16(sbase + B_H_OFF + so, Bh + gb);
            cpa16(sbase + B_L_OFF + so, Bl + gb);
        }
    };

    load_stage(0, 0); CP_COMMIT();
    load_stage(1, BKc); CP_COMMIT();

    float acc[2][8][4];
#pragma unroll
    for (int mi = 0; mi < 2; mi++)
#pragma unroll
        for (int ni = 0; ni < 8; ni++)
#pragma unroll
            for (int e = 0; e < 4; e++) acc[mi][ni][e] = 0.f;

    const int lrow = lane & 15;
    const int lchunk = (lane >> 4) * 16;

    for (int c = 0; c < nch; c++) {
        CP_WAIT1();
        __syncthreads();

        int cn = c + STAGES - 1;
        if (cn < nch) load_stage(cn % STAGES, cn * BKc);
        CP_COMMIT();

        const uint32_t sbase = sb + (c % STAGES) * STG_BYTES;
        const uint32_t sAh = sbase + A_H_OFF, sAl = sbase + A_L_OFF;
        const uint32_t sBh = sbase + B_H_OFF, sBl = sbase + B_L_OFF;

#pragma unroll
        for (int ks = 0; ks < 4; ks++) {
            const int kb = ks * 32 + lchunk;
            uint32_t ah[2][4], al[2][4];
#pragma unroll
            for (int mi = 0; mi < 2; mi++) {
                uint32_t bo = sw128((uint32_t)((wm + mi * 16 + lrow) * 128 + kb));
                ldm4(ah[mi], sAh + bo);
                ldm4(al[mi], sAl + bo);
            }
            uint32_t bh[4][4], bl[4][4];
#pragma unroll
            for (int g = 0; g < 4; g++) {
                uint32_t bo = sw128((uint32_t)((wn + g * 16 + lrow) * 128 + kb));
                ldm4(bh[g], sBh + bo);
                ldm4(bl[g], sBl + bo);
            }
#pragma unroll
            for (int mi = 0; mi < 2; mi++)
#pragma unroll
                for (int ni = 0; ni < 8; ni++) {
                    int g = ni >> 1, hf = ni & 1;
                    mma16816(acc[mi][ni], ah[mi], bh[g][hf], bh[g][hf + 2]);
                    mma16816(acc[mi][ni], ah[mi], bl[g][hf], bl[g][hf + 2]);
                    mma16816(acc[mi][ni], al[mi], bh[g][hf], bh[g][hf + 2]);
                }
        }
    }

    const int gro = lane >> 2, thr = lane & 3;
#pragma unroll
    for (int mi = 0; mi < 2; mi++) {
        int r0 = rowBase + wm + mi * 16 + gro;
#pragma unroll
        for (int ni = 0; ni < 8; ni++) {
            int cb = colBase + wn + ni * 8 + thr * 2;
            float bx = bias[cb], by = bias[cb + 1];
            float2 o0, o1;
            o0.x = acc[mi][ni][0] + bx; o0.y = acc[mi][ni][1] + by;
            o1.x = acc[mi][ni][2] + bx; o1.y = acc[mi][ni][3] + by;
            *(float2*)(Cm + (size_t)r0 * N + cb) = o0;
            *(float2*)(Cm + (size_t)(r0 + 8) * N + cb) = o1;
        }
    }
}

// ---------------------------------------------------------------------------
// HMMA flash attention v3: 64 q-rows/CTA, 4 warps, Q fragments in REGISTERS,
// 32-row KV tiles double-buffered via cp.async, 2 CTAs/SM.
// SMEM: Q staging 32KB @0; 2 KV stages of 32KB @32768 (KH,KL,VH,VL 8KB each).
// ---------------------------------------------------------------------------
#define QSTG 0
#define QSTG_L 16384
#define KV0 32768
#define KVSTB 32768
#define KH_O 0
#define KL_O 8192
#define VH_O 16384
#define VL_O 24576
#define ATTN3_DSM (32768 + 2 * 32768 + 1024)

__global__ __launch_bounds__(128, 2)
void attn_hmma3(const __nv_bfloat16* __restrict__ qh, const __nv_bfloat16* __restrict__ ql,
                const __nv_bfloat16* __restrict__ kh, const __nv_bfloat16* __restrict__ kl,
                const __nv_bfloat16* __restrict__ vh, const __nv_bfloat16* __restrict__ vl,
                __nv_bfloat16* __restrict__ yh, __nv_bfloat16* __restrict__ yl)
{
    extern __shared__ char asmem[];
    const uint32_t raw = smem_u32(asmem);
    const uint32_t sb = (raw + 1023u) & ~1023u;

    const int qt = blockIdx.x, h = blockIdx.y, b = blockIdx.z;
    const int qb = qt * 64;
    const int tid = threadIdx.x;
    const int wid = tid >> 5, lane = tid & 31;
    const int wq0 = wid * 16;              // warp's q-row offset (4 warps x 16)
    const int lrow = lane & 15;
    const int lch = (lane >> 4) * 16;
    const int gro = lane >> 2, thr = lane & 3;
    const uint32_t rx = ((uint32_t)(lrow & 7)) << 4;

    // ---- Stage Q tile (64 rows x 128 cols hi/lo) via cp.async ----
#pragma unroll
    for (int rep = 0; rep < 8; rep++) {
        int idx = tid + rep * 128;          // [0,1024)
        int row = idx >> 4, ch = idx & 15;
        uint32_t so = (uint32_t)row * 256 +
                      (((uint32_t)(ch * 16)) ^ (((uint32_t)(row & 7)) << 4));
        size_t g = ((size_t)(b * T_ + qb + row)) * C_ + h * DH + ch * 8;
        cpa16(sb + QSTG + so, qh + g);
        cpa16(sb + QSTG_L + so, ql + g);
    }
    CP_COMMIT();

    auto loadKV = [&](int st, int j2) {
        uint32_t stb = sb + KV0 + st * KVSTB;
        size_t grow = ((size_t)(b * T_ + j2 * 32)) * C_ + h * DH;
#pragma unroll
        for (int rep = 0; rep < 4; rep++) {
            int idx = tid + rep * 128;      // [0,512)
            int row = idx >> 4, ch = idx & 15;
            uint32_t so = (uint32_t)row * 256 +
                          (((uint32_t)(ch * 16)) ^ (((uint32_t)(row & 7)) << 4));
            size_t g = grow + (size_t)row * C_ + ch * 8;
            cpa16(stb + KH_O + so, kh + g);
            cpa16(stb + KL_O + so, kl + g);
            cpa16(stb + VH_O + so, vh + g);
            cpa16(stb + VL_O + so, vl + g);
        }
    };

    loadKV(0, 0);
    CP_COMMIT();

    // ---- Wait Q staged (allow KV0 pending), pull Q fragments to registers ----
    CP_WAIT1();
    __syncthreads();
    uint32_t aqh[8][4], aql[8][4];
#pragma unroll
    for (int kc = 0; kc < 8; kc++) {
        uint32_t off = (uint32_t)(wq0 + lrow) * 256 +
                       (((uint32_t)(kc * 32 + lch)) ^ rx);
        ldm4(aqh[kc], sb + QSTG + off);
        ldm4(aql[kc], sb + QSTG_L + off);
    }

    float m0 = -INFINITY, m1 = -INFINITY, l0 = 0.f, l1 = 0.f;
    float O[16][4];
#pragma unroll
    for (int i = 0; i < 16; i++)
#pragma unroll
        for (int e = 0; e < 4; e++) O[i][e] = 0.f;

    const int ntiles = 2 * qt + 2;          // kv tiles of 32 rows, up to qb+64
    for (int j = 0; j < ntiles; j++) {
        const int kvg = j * 32;
        if (j + 1 < ntiles) {
            loadKV((j + 1) & 1, j + 1);     // stage safe: freed at end of j-1
            CP_COMMIT();
            CP_WAIT1();                     // tile j landed; j+1 in flight
        } else {
            CP_WAIT0();
        }
        __syncthreads();

        const uint32_t stb = sb + KV0 + (j & 1) * KVSTB;
        const uint32_t sKH = stb + KH_O, sKL = stb + KL_O;
        const uint32_t sVH = stb + VH_O, sVL = stb + VL_O;

        // ---- S = Q K^T (3-term bf16x3), S in log2 domain ----
        float c[4][4];
#pragma unroll
        for (int nt = 0; nt < 4; nt++)
#pragma unroll
            for (int e = 0; e < 4; e++) c[nt][e] = 0.f;

#pragma unroll
        for (int kc = 0; kc < 8; kc++) {
            const uint32_t kb = (uint32_t)(kc * 32 + lch);
#pragma unroll
            for (int g4 = 0; g4 < 2; g4++) {
                uint32_t off = (uint32_t)(g4 * 16 + lrow) * 256 + (kb ^ rx);
                uint32_t bh[4], bl[4];
                ldm4(bh, sKH + off);
                ldm4(bl, sKL + off);
#pragma unroll
                for (int hf = 0; hf < 2; hf++) {
                    int nt = g4 * 2 + hf;
                    mma16816(c[nt], aqh[kc], bh[hf], bh[hf + 2]);
                    mma16816(c[nt], aqh[kc], bl[hf], bl[hf + 2]);
                    mma16816(c[nt], aql[kc], bh[hf], bh[hf + 2]);
                }
            }
        }

        // ---- Causal mask ----
        const int row_lo = qb + wq0 + gro;
        const int row_hi = row_lo + 8;
        if (kvg + 31 > qb + wq0) {
#pragma unroll
            for (int nt = 0; nt < 4; nt++) {
                int cbase = kvg + nt * 8 + 2 * thr;
                if (cbase > row_lo)     c[nt][0] = -1e30f;
                if (cbase + 1 > row_lo) c[nt][1] = -1e30f;
                if (cbase > row_hi)     c[nt][2] = -1e30f;
                if (cbase + 1 > row_hi) c[nt][3] = -1e30f;
            }
        }

        // ---- Online softmax (base-2) ----
        float mt0 = -1e30f, mt1 = -1e30f;
#pragma unroll
        for (int nt = 0; nt < 4; nt++) {
            mt0 = fmaxf(mt0, fmaxf(c[nt][0], c[nt][1]));
            mt1 = fmaxf(mt1, fmaxf(c[nt][2], c[nt][3]));
        }
        mt0 = fmaxf(mt0, __shfl_xor_sync(0xffffffffu, mt0, 1));
        mt0 = fmaxf(mt0, __shfl_xor_sync(0xffffffffu, mt0, 2));
        mt1 = fmaxf(mt1, __shfl_xor_sync(0xffffffffu, mt1, 1));
        mt1 = fmaxf(mt1, __shfl_xor_sync(0xffffffffu, mt1, 2));
        float mn0 = fmaxf(m0, mt0), mn1 = fmaxf(m1, mt1);
        float cor0 = ex2f(m0 - mn0), cor1 = ex2f(m1 - mn1);
        float s0 = 0.f, s1 = 0.f;
#pragma unroll
        for (int nt = 0; nt < 4; nt++) {
            c[nt][0] = ex2f(c[nt][0] - mn0); s0 += c[nt][0];
            c[nt][1] = ex2f(c[nt][1] - mn0); s0 += c[nt][1];
            c[nt][2] = ex2f(c[nt][2] - mn1); s1 += c[nt][2];
            c[nt][3] = ex2f(c[nt][3] - mn1); s1 += c[nt][3];
        }
        s0 += __shfl_xor_sync(0xffffffffu, s0, 1);
        s0 += __shfl_xor_sync(0xffffffffu, s0, 2);
        s1 += __shfl_xor_sync(0xffffffffu, s1, 1);
        s1 += __shfl_xor_sync(0xffffffffu, s1, 2);
        l0 = l0 * cor0 + s0; m0 = mn0;
        l1 = l1 * cor1 + s1; m1 = mn1;
#pragma unroll
        for (int i = 0; i < 16; i++) {
            O[i][0] *= cor0; O[i][1] *= cor0;
            O[i][2] *= cor1; O[i][3] *= cor1;
        }

        // ---- O += P V (3-term; P hi/lo built in registers) ----
        const uint32_t rxv = ((uint32_t)(lane & 7)) << 4;
        const uint32_t colb = (uint32_t)((lane >> 3) & 1) * 16;
#pragma unroll
        for (int kc2 = 0; kc2 < 2; kc2++) {
            uint32_t aph[4], apl[4];
            {
                float p00 = c[2 * kc2][0], p01 = c[2 * kc2][1];
                float p10 = c[2 * kc2][2], p11 = c[2 * kc2][3];
                float p20 = c[2 * kc2 + 1][0], p21 = c[2 * kc2 + 1][1];
                float p30 = c[2 * kc2 + 1][2], p31 = c[2 * kc2 + 1][3];
                aph[0] = packbf(p00, p01);
                aph[1] = packbf(p10, p11);
                aph[2] = packbf(p20, p21);
                aph[3] = packbf(p30, p31);
                __nv_bfloat162* t;
                t = (__nv_bfloat162*)&aph[0];
                apl[0] = packbf(p00 - __bfloat162float(t->x), p01 - __bfloat162float(t->y));
                t = (__nv_bfloat162*)&aph[1];
                apl[1] = packbf(p10 - __bfloat162float(t->x), p11 - __bfloat162float(t->y));
                t = (__nv_bfloat162*)&aph[2];
                apl[2] = packbf(p20 - __bfloat162float(t->x), p21 - __bfloat162float(t->y));
                t = (__nv_bfloat162*)&aph[3];
                apl[3] = packbf(p30 - __bfloat162float(t->x), p31 - __bfloat162float(t->y));
            }
            const uint32_t vrow = (uint32_t)(kc2 * 16 + (lane & 7) + (lane >> 4) * 8);
#pragma unroll
            for (int gg = 0; gg < 8; gg++) {
                uint32_t off = vrow * 256 + (((uint32_t)(gg * 32) + colb) ^ rxv);
                uint32_t vhf[4], vlf[4];
                ldm4t(vhf, sVH + off);
                ldm4t(vlf, sVL + off);
#pragma unroll
                for (int hf = 0; hf < 2; hf++) {
                    int nt2 = gg * 2 + hf;
                    mma16816(O[nt2], aph, vhf[hf], vhf[hf + 2]);
                    mma16816(O[nt2], aph, vlf[hf], vlf[hf + 2]);
                    mma16816(O[nt2], apl, vhf[hf], vhf[hf + 2]);
                }
            }
        }
        __syncthreads();   // all warps done with stage (j&1) before overwrite
    }

    // ---- Epilogue: normalize, split hi/lo, store y bf16 arrays ----
    const float il0 = 1.f / l0, il1 = 1.f / l1;
    const int row_lo = qb + wq0 + gro;
    size_t r0o = (size_t)(b * T_ + row_lo) * C_;
    size_t r1o = (size_t)(b * T_ + row_lo + 8) * C_;
#pragma unroll
    for (int nt2 = 0; nt2 < 16; nt2++) {
        int col = h * DH + nt2 * 8 + 2 * thr;
        float a0 = O[nt2][0] * il0, a1 = O[nt2][1] * il0;
        float b0 = O[nt2][2] * il1, b1 = O[nt2][3] * il1;
        uint32_t h0 = packbf(a0, a1);
        __nv_bfloat162 hv0 = *(__nv_bfloat162*)&h0;
        uint32_t l0w = packbf(a0 - __bfloat162float(hv0.x), a1 - __bfloat162float(hv0.y));
        uint32_t h1 = packbf(b0, b1);
        __nv_bfloat162 hv1 = *(__nv_bfloat162*)&h1;
        uint32_t l1w = packbf(b0 - __bfloat162float(hv1.x), b1 - __bfloat162float(hv1.y));
        *(uint32_t*)(yh + r0o + col) = h0;
        *(uint32_t*)(yl + r0o + col) = l0w;
        *(uint32_t*)(yh + r1o + col) = h1;
        *(uint32_t*)(yl + r1o + col) = l1w;
    }
}

// ---------------------------------------------------------------------------
// Launch
// ---------------------------------------------------------------------------
extern "C" void kernel_launch(void* const* d_in, const int* in_sizes, int n_in,
                              void* d_out, int out_size)
{
    (void)in_sizes; (void)n_in; (void)out_size;
    const float* x      = (const float*)d_in[0];
    const float* w_qkv  = (const float*)d_in[1];
    const float* b_qkv  = (const float*)d_in[2];
    const float* w_proj = (const float*)d_in[3];
    const float* b_proj = (const float*)d_in[4];
    float* out = (float*)d_out;

    void *p_xh, *p_xl, *p_yh, *p_yl, *p_wqh, *p_wql, *p_wph, *p_wpl;
    void *p_qh, *p_ql, *p_kh, *p_kl, *p_vh, *p_vl;
    cudaGetSymbolAddress(&p_xh, g_xc_h);
    cudaGetSymbolAddress(&p_xl, g_xc_l);
    cudaGetSymbolAddress(&p_yh, g_yc_h);
    cudaGetSymbolAddress(&p_yl, g_yc_l);
    cudaGetSymbolAddress(&p_wqh, g_wq_h);
    cudaGetSymbolAddress(&p_wql, g_wq_l);
    cudaGetSymbolAddress(&p_wph, g_wp_h);
    cudaGetSymbolAddress(&p_wpl, g_wp_l);
    cudaGetSymbolAddress(&p_qh, g_qh);
    cudaGetSymbolAddress(&p_ql, g_ql);
    cudaGetSymbolAddress(&p_kh, g_kh);
    cudaGetSymbolAddress(&p_kl, g_kl);
    cudaGetSymbolAddress(&p_vh, g_vh);
    cudaGetSymbolAddress(&p_vl, g_vl);

    cudaFuncSetAttribute(gemm_qkv_rope,
                         cudaFuncAttributeMaxDynamicSharedMemorySize, GEMM_DSM);
    cudaFuncSetAttribute(gemm_hmma_bf16x3,
                         cudaFuncAttributeMaxDynamicSharedMemorySize, GEMM_DSM);
    cudaFuncSetAttribute(attn_hmma3,
                         cudaFuncAttributeMaxDynamicSharedMemorySize, ATTN3_DSM);

    // 0) Weight transpose+split and x split
    wconv<<<dim3(THREE_C / 32, C_ / 32), dim3(32, 8)>>>(
        w_qkv, (__nv_bfloat16*)p_wqh, (__nv_bfloat16*)p_wql, C_, THREE_C);
    wconv<<<dim3(C_ / 32, C_ / 32), dim3(32, 8)>>>(
        w_proj, (__nv_bfloat16*)p_wph, (__nv_bfloat16*)p_wpl, C_, C_);
    {
        long n8 = (long)M_ * C_ / 8;
        convert_hilo<<<(int)((n8 + 255) / 256), 256>>>(
            x, (__nv_bfloat16*)p_xh, (__nv_bfloat16*)p_xl, n8);
    }

    // 1) QKV GEMM + fused bias + RoPE + scale + bf16 hi/lo split
    gemm_qkv_rope<<<dim3(THREE_C / 128, M_ / 128), GEMM_THREADS, GEMM_DSM>>>(
        (const __nv_bfloat16*)p_xh, (const __nv_bfloat16*)p_xl,
        (const __nv_bfloat16*)p_wqh, (const __nv_bfloat16*)p_wql,
        b_qkv,
        (__nv_bfloat16*)p_qh, (__nv_bfloat16*)p_ql,
        (__nv_bfloat16*)p_kh, (__nv_bfloat16*)p_kl,
        (__nv_bfloat16*)p_vh, (__nv_bfloat16*)p_vl);

    // 2) Causal flash attention (HMMA bf16x3, 2 CTA/SM, Q in regs) -> y hi/lo
    {
        dim3 grid(T_ / 64, H_, B_);
        attn_hmma3<<<grid, 128, ATTN3_DSM>>>(
            (const __nv_bfloat16*)p_qh, (const __nv_bfloat16*)p_ql,
            (const __nv_bfloat16*)p_kh, (const __nv_bfloat16*)p_kl,
            (const __nv_bfloat16*)p_vh, (const __nv_bfloat16*)p_vl,
            (__nv_bfloat16*)p_yh, (__nv_bfloat16*)p_yl);
    }

    // 3) out = y @ w_proj + b_proj (HMMA bf16x3, fp32 out)
    gemm_hmma_bf16x3<<<dim3(C_ / 128, M_ / 128), GEMM_THREADS, GEMM_DSM>>>(
        (const __nv_bfloat16*)p_yh, (const __nv_bfloat16*)p_yl,
        (const __nv_bfloat16*)p_wph, (const __nv_bfloat16*)p_wpl,
        b_proj, out, C_, C_);
}